// round 1
// baseline (speedup 1.0000x reference)
#include <cuda_runtime.h>
#include <cstddef>

#define NT    4096      // H*W tokens
#define CH    256       // hidden channels
#define CIN   512       // input channels
#define BATCH 4
#define BN    64        // attention n-tile
#define BM    64        // attention m-tile
#define KC    32        // k-chunk for S gemm
#define HPAD  (CH + 4)

// ---------------- scratch (no allocation allowed in kernel_launch) ----------------
__device__ float d_f  [(size_t)BATCH * CH * NT];   // f  [b][d][n]
__device__ float d_g  [(size_t)BATCH * CH * NT];   // g  [b][d][n]
__device__ float d_hT [(size_t)BATCH * NT * CH];   // hT [b][n][d]
__device__ float d_fcs[(size_t)BATCH * CH * NT];   // Fcs[b][d][n]
__device__ float d_mean[2 * BATCH * CIN];          // [which][b][c]
__device__ float d_inv [2 * BATCH * CIN];

__device__ __forceinline__ float relu6f(float x) { return fminf(fmaxf(x, 0.0f), 6.0f); }

// ---------------- per-(b,c) instance-norm stats, ddof=1 ----------------
__global__ __launch_bounds__(256) void stats_kernel(const float* __restrict__ Fc,
                                                    const float* __restrict__ Fs) {
    int inst  = blockIdx.x;              // b*CIN + c
    int which = blockIdx.y;              // 0 -> Fc, 1 -> Fs
    const float* src = (which ? Fs : Fc) + (size_t)inst * NT;
    int tid = threadIdx.x;
    float s = 0.f, ss = 0.f;
    for (int e = tid; e < NT / 4; e += 256) {
        float4 v = ((const float4*)src)[e];
        s  += v.x + v.y + v.z + v.w;
        ss += v.x * v.x + v.y * v.y + v.z * v.z + v.w * v.w;
    }
    for (int o = 16; o; o >>= 1) {
        s  += __shfl_xor_sync(0xffffffffu, s, o);
        ss += __shfl_xor_sync(0xffffffffu, ss, o);
    }
    __shared__ float sb[8], ssb[8];
    if ((tid & 31) == 0) { sb[tid >> 5] = s; ssb[tid >> 5] = ss; }
    __syncthreads();
    if (tid == 0) {
        s = 0.f; ss = 0.f;
        for (int w = 0; w < 8; w++) { s += sb[w]; ss += ssb[w]; }
        float mean = s / (float)NT;
        float var  = (ss - s * mean) / (float)(NT - 1);
        d_mean[which * BATCH * CIN + inst] = mean;
        d_inv [which * BATCH * CIN + inst] = rsqrtf(var + 1e-5f);
    }
}

// ---------------- generic 1x1-conv GEMM: Y[r,n] = relu6(sum_k W[r,k]*X[k,n] + b[r]) ----
// Optional on-the-fly instance-norm of X (mean/inv per [b][k]).
// transOut=1 writes Y as [n][R] (used for h so attention reads hT conflict-free).
__global__ __launch_bounds__(256) void conv_kernel(
    const float* __restrict__ X, const float* __restrict__ W, const float* __restrict__ bias,
    const float* __restrict__ mean, const float* __restrict__ inv,
    float* __restrict__ Y, int R, int K, int transOut)
{
    __shared__ float Wsm[16][68];   // [k][r], pad 68 (16B-aligned rows, low write conflicts)
    __shared__ float Xsm[16][64];   // [k][n]
    int b  = blockIdx.z;
    int n0 = blockIdx.x * 64;
    int r0 = blockIdx.y * 64;
    const float* Xb = X + (size_t)b * K * NT;
    int tid = threadIdx.x;
    int tx = tid & 15, ty = tid >> 4;

    float acc[4][4];
#pragma unroll
    for (int i = 0; i < 4; i++)
#pragma unroll
        for (int j = 0; j < 4; j++) acc[i][j] = 0.f;

    int wr = tid >> 2;           // 0..63  W-tile row
    int wk = (tid & 3) * 4;      // 0,4,8,12
    int xk = tid >> 4;           // 0..15  X-tile k-row
    int xj = (tid & 15) * 4;     // n within tile

    for (int k0 = 0; k0 < K; k0 += 16) {
        __syncthreads();
        float4 wv = *(const float4*)(W + (size_t)(r0 + wr) * K + k0 + wk);
        Wsm[wk + 0][wr] = wv.x; Wsm[wk + 1][wr] = wv.y;
        Wsm[wk + 2][wr] = wv.z; Wsm[wk + 3][wr] = wv.w;
        float4 xv = *(const float4*)(Xb + (size_t)(k0 + xk) * NT + n0 + xj);
        if (mean) {
            float mu = mean[b * K + k0 + xk];
            float iv = inv [b * K + k0 + xk];
            xv.x = (xv.x - mu) * iv; xv.y = (xv.y - mu) * iv;
            xv.z = (xv.z - mu) * iv; xv.w = (xv.w - mu) * iv;
        }
        *(float4*)(&Xsm[xk][xj]) = xv;
        __syncthreads();
#pragma unroll
        for (int k = 0; k < 16; k++) {
            float4 av = *(const float4*)(&Wsm[k][ty * 4]);
            float4 bv = *(const float4*)(&Xsm[k][tx * 4]);
            float a[4]  = {av.x, av.y, av.z, av.w};
            float bb[4] = {bv.x, bv.y, bv.z, bv.w};
#pragma unroll
            for (int i = 0; i < 4; i++)
#pragma unroll
                for (int j = 0; j < 4; j++) acc[i][j] += a[i] * bb[j];
        }
    }

    if (!transOut) {
        float* Yb = Y + (size_t)b * R * NT;
#pragma unroll
        for (int i = 0; i < 4; i++) {
            int r = r0 + ty * 4 + i;
            float bs = bias[r];
            float4 o;
            o.x = relu6f(acc[i][0] + bs); o.y = relu6f(acc[i][1] + bs);
            o.z = relu6f(acc[i][2] + bs); o.w = relu6f(acc[i][3] + bs);
            *(float4*)(Yb + (size_t)r * NT + n0 + tx * 4) = o;
        }
    } else {
        float* Yb = Y + (size_t)b * NT * R;
        float bs0 = bias[r0 + ty * 4 + 0], bs1 = bias[r0 + ty * 4 + 1];
        float bs2 = bias[r0 + ty * 4 + 2], bs3 = bias[r0 + ty * 4 + 3];
#pragma unroll
        for (int j = 0; j < 4; j++) {
            int n = n0 + tx * 4 + j;
            float4 o;
            o.x = relu6f(acc[0][j] + bs0); o.y = relu6f(acc[1][j] + bs1);
            o.z = relu6f(acc[2][j] + bs2); o.w = relu6f(acc[3][j] + bs3);
            *(float4*)(Yb + (size_t)n * R + r0 + ty * 4) = o;
        }
    }
}

// ---------------- fused flash attention: Fcs[b,d,n] = sum_m softmax_m(f.g) * h[d,m] ----
__global__ __launch_bounds__(256, 1) void attn_kernel(
    const float* __restrict__ fb, const float* __restrict__ gb,
    const float* __restrict__ hTb, float* __restrict__ fcs)
{
    extern __shared__ float smbuf[];
    float* fsm = smbuf;                  // [CH][BN]      64 KB, resident
    float* hsm = fsm + CH * BN;          // [BM][HPAD]    ~66 KB per m-tile
    float* gsm = hsm + BM * HPAD;        // [KC][BM]      8 KB chunk
    float* Psm = gsm + KC * BM;          // [BN][BM]      16 KB

    int b  = blockIdx.y;
    int n0 = blockIdx.x * BN;
    int tid = threadIdx.x;
    int tx = tid & 15, ty = tid >> 4;
    const float* f  = fb  + (size_t)b * CH * NT;
    const float* g  = gb  + (size_t)b * CH * NT;
    const float* hT = hTb + (size_t)b * NT * CH;

    // resident f tile
    for (int e = tid; e < CH * BN / 4; e += 256) {
        int d = e >> 4, j4 = (e & 15) * 4;
        *(float4*)(fsm + d * BN + j4) = *(const float4*)(f + (size_t)d * NT + n0 + j4);
    }

    float m_i[4], l_i[4], acc[4][16];
#pragma unroll
    for (int i = 0; i < 4; i++) {
        m_i[i] = -1e30f; l_i[i] = 0.f;
#pragma unroll
        for (int q = 0; q < 16; q++) acc[i][q] = 0.f;
    }

    for (int mt = 0; mt < NT / BM; mt++) {
        int m0 = mt * BM;
        __syncthreads();   // prev PV reads of hsm/Psm (and fsm writes at mt=0) complete

        // load hsm[m][d] (hT is already [n][d]: coalesced, conflict-free)
        for (int e = tid; e < BM * CH / 4; e += 256) {
            int m = e >> 6, dg = (e & 63) * 4;
            *(float4*)(hsm + m * HPAD + dg) = *(const float4*)(hT + (size_t)(m0 + m) * CH + dg);
        }

        float S[4][4];
#pragma unroll
        for (int i = 0; i < 4; i++)
#pragma unroll
            for (int j = 0; j < 4; j++) S[i][j] = 0.f;

        for (int kc = 0; kc < CH / KC; kc++) {
            if (kc) __syncthreads();
            for (int e = tid; e < KC * BM / 4; e += 256) {
                int kk = e >> 4, j4 = (e & 15) * 4;
                *(float4*)(gsm + kk * BM + j4) =
                    *(const float4*)(g + (size_t)(kc * KC + kk) * NT + m0 + j4);
            }
            __syncthreads();
#pragma unroll
            for (int k = 0; k < KC; k++) {
                float4 av = *(const float4*)(fsm + (kc * KC + k) * BN + ty * 4);
                float4 bv = *(const float4*)(gsm + k * BM + tx * 4);
                float a[4]  = {av.x, av.y, av.z, av.w};
                float bb[4] = {bv.x, bv.y, bv.z, bv.w};
#pragma unroll
                for (int i = 0; i < 4; i++)
#pragma unroll
                    for (int j = 0; j < 4; j++) S[i][j] += a[i] * bb[j];
            }
        }

        // online softmax (rows live on 16-lane tx-groups within a warp)
#pragma unroll
        for (int i = 0; i < 4; i++) {
            float mx = fmaxf(fmaxf(S[i][0], S[i][1]), fmaxf(S[i][2], S[i][3]));
#pragma unroll
            for (int o = 1; o < 16; o <<= 1) mx = fmaxf(mx, __shfl_xor_sync(0xffffffffu, mx, o));
            float mnew = fmaxf(m_i[i], mx);
            float corr = __expf(m_i[i] - mnew);
            m_i[i] = mnew;
            float p0 = __expf(S[i][0] - mnew), p1 = __expf(S[i][1] - mnew);
            float p2 = __expf(S[i][2] - mnew), p3 = __expf(S[i][3] - mnew);
            float rs = p0 + p1 + p2 + p3;
#pragma unroll
            for (int o = 1; o < 16; o <<= 1) rs += __shfl_xor_sync(0xffffffffu, rs, o);
            l_i[i] = l_i[i] * corr + rs;
#pragma unroll
            for (int q = 0; q < 16; q++) acc[i][q] *= corr;
            *(float4*)(Psm + (ty * 4 + i) * BM + tx * 4) = make_float4(p0, p1, p2, p3);
        }
        __syncthreads();

        // acc[n][d] += P[n,m] * h[d,m]  (d = dd*64 + tx*4 + j : contiguous lane float4s)
#pragma unroll 4
        for (int m = 0; m < BM; m++) {
            float p[4];
#pragma unroll
            for (int i = 0; i < 4; i++) p[i] = Psm[(ty * 4 + i) * BM + m];
#pragma unroll
            for (int dd = 0; dd < 4; dd++) {
                float4 hv = *(const float4*)(hsm + m * HPAD + dd * 64 + tx * 4);
                float hh[4] = {hv.x, hv.y, hv.z, hv.w};
#pragma unroll
                for (int i = 0; i < 4; i++)
#pragma unroll
                    for (int j = 0; j < 4; j++) acc[i][dd * 4 + j] += p[i] * hh[j];
            }
        }
    }

    // normalize and write Fcs[b][d][n]
    float* out = fcs + (size_t)b * CH * NT;
#pragma unroll
    for (int i = 0; i < 4; i++) {
        float invl = 1.f / l_i[i];
        int n = n0 + ty * 4 + i;
#pragma unroll
        for (int dd = 0; dd < 4; dd++)
#pragma unroll
            for (int j = 0; j < 4; j++)
                out[(size_t)(dd * 64 + tx * 4 + j) * NT + n] = acc[i][dd * 4 + j] * invl;
    }
}

// ---------------- launch ----------------
extern "C" void kernel_launch(void* const* d_in, const int* in_sizes, int n_in,
                              void* d_out, int out_size) {
    const float* Fc    = (const float*)d_in[0];
    const float* Fs    = (const float*)d_in[1];
    const float* f_w   = (const float*)d_in[2];
    const float* f_b   = (const float*)d_in[3];
    const float* g_w   = (const float*)d_in[4];
    const float* g_b   = (const float*)d_in[5];
    const float* h_w   = (const float*)d_in[6];
    const float* h_b   = (const float*)d_in[7];
    const float* out_w = (const float*)d_in[8];
    const float* out_b = (const float*)d_in[9];
    float* out = (float*)d_out;

    float *pf, *pg, *phT, *pfcs, *pmean, *pinv;
    cudaGetSymbolAddress((void**)&pf,    d_f);
    cudaGetSymbolAddress((void**)&pg,    d_g);
    cudaGetSymbolAddress((void**)&phT,   d_hT);
    cudaGetSymbolAddress((void**)&pfcs,  d_fcs);
    cudaGetSymbolAddress((void**)&pmean, d_mean);
    cudaGetSymbolAddress((void**)&pinv,  d_inv);

    const size_t ATTN_SMEM =
        (size_t)(CH * BN + BM * HPAD + KC * BM + BN * BM) * sizeof(float);  // 156672 B
    cudaFuncSetAttribute(attn_kernel, cudaFuncAttributeMaxDynamicSharedMemorySize,
                         (int)ATTN_SMEM);

    stats_kernel<<<dim3(BATCH * CIN, 2), 256>>>(Fc, Fs);

    // f = relu6(f_w @ mvn(Fc) + f_b)
    conv_kernel<<<dim3(NT / 64, CH / 64, BATCH), 256>>>(Fc, f_w, f_b, pmean, pinv,
                                                        pf, CH, CIN, 0);
    // g = relu6(g_w @ mvn(Fs) + g_b)
    conv_kernel<<<dim3(NT / 64, CH / 64, BATCH), 256>>>(Fs, g_w, g_b,
                                                        pmean + BATCH * CIN,
                                                        pinv  + BATCH * CIN,
                                                        pg, CH, CIN, 0);
    // h = relu6(h_w @ Fs + h_b), stored transposed [n][d]
    conv_kernel<<<dim3(NT / 64, CH / 64, BATCH), 256>>>(Fs, h_w, h_b, nullptr, nullptr,
                                                        phT, CH, CIN, 1);

    attn_kernel<<<dim3(NT / BN, BATCH), 256, ATTN_SMEM>>>(pf, pg, phT, pfcs);

    // out = relu6(out_w @ Fcs + out_b)
    conv_kernel<<<dim3(NT / 64, CIN / 64, BATCH), 256>>>(pfcs, out_w, out_b, nullptr, nullptr,
                                                         out, CIN, CH, 0);
}

// round 2
// speedup vs baseline: 1.0614x; 1.0614x over previous
#include <cuda_runtime.h>
#include <cstddef>

#define NT    4096      // H*W tokens
#define CH    256       // hidden channels
#define CIN   512       // input channels
#define BATCH 4
#define BN    64        // attention n-tile (rows per CTA)
#define BM    128       // attention m-tile per iteration
#define KC    32        // k-chunk for S gemm

// ---------------- scratch (no allocation allowed in kernel_launch) ----------------
__device__ float d_f  [(size_t)BATCH * CH * NT];   // f  [b][d][n]
__device__ float d_g  [(size_t)BATCH * CH * NT];   // g  [b][d][n]
__device__ float d_hT [(size_t)BATCH * NT * CH];   // hT [b][n][d]
__device__ float d_fcs[(size_t)BATCH * CH * NT];   // Fcs[b][d][n]
__device__ float d_mean[2 * BATCH * CIN];          // [which][b][c]
__device__ float d_inv [2 * BATCH * CIN];

__device__ __forceinline__ float relu6f(float x) { return fminf(fmaxf(x, 0.0f), 6.0f); }

// packed fp32x2 FMA (Blackwell FFMA2) : d += a * b  (elementwise on pairs)
__device__ __forceinline__ void ffma2(float2& d, const float2 a, const float2 b) {
    asm("fma.rn.f32x2 %0, %1, %2, %0;"
        : "+l"(*reinterpret_cast<unsigned long long*>(&d))
        : "l"(*reinterpret_cast<const unsigned long long*>(&a)),
          "l"(*reinterpret_cast<const unsigned long long*>(&b)));
}
__device__ __forceinline__ float2 f2b(float a) { return make_float2(a, a); }

// ---------------- per-(b,c) instance-norm stats, ddof=1 ----------------
__global__ __launch_bounds__(256) void stats_kernel(const float* __restrict__ Fc,
                                                    const float* __restrict__ Fs) {
    int inst  = blockIdx.x;              // b*CIN + c
    int which = blockIdx.y;              // 0 -> Fc, 1 -> Fs
    const float* src = (which ? Fs : Fc) + (size_t)inst * NT;
    int tid = threadIdx.x;
    float s = 0.f, ss = 0.f;
    for (int e = tid; e < NT / 4; e += 256) {
        float4 v = ((const float4*)src)[e];
        s  += v.x + v.y + v.z + v.w;
        ss += v.x * v.x + v.y * v.y + v.z * v.z + v.w * v.w;
    }
    for (int o = 16; o; o >>= 1) {
        s  += __shfl_xor_sync(0xffffffffu, s, o);
        ss += __shfl_xor_sync(0xffffffffu, ss, o);
    }
    __shared__ float sb[8], ssb[8];
    if ((tid & 31) == 0) { sb[tid >> 5] = s; ssb[tid >> 5] = ss; }
    __syncthreads();
    if (tid == 0) {
        s = 0.f; ss = 0.f;
        for (int w = 0; w < 8; w++) { s += sb[w]; ss += ssb[w]; }
        float mean = s / (float)NT;
        float var  = (ss - s * mean) / (float)(NT - 1);
        d_mean[which * BATCH * CIN + inst] = mean;
        d_inv [which * BATCH * CIN + inst] = rsqrtf(var + 1e-5f);
    }
}

// ---------------- 1x1-conv GEMM: Y[r,n] = relu6(sum_k W[r,k]*X[k,n] + b[r]) -------
// 128(r) x 64(n) tile, 256 threads, 8x4 per thread, f32x2 packed FMA.
// Optional on-the-fly instance-norm of X. transOut=1 writes Y as [n][R].
__global__ __launch_bounds__(256) void conv_kernel(
    const float* __restrict__ X, const float* __restrict__ W, const float* __restrict__ bias,
    const float* __restrict__ mean, const float* __restrict__ inv,
    float* __restrict__ Y, int R, int K, int transOut)
{
    __shared__ float Wsm[16][128];  // [k][r] transposed
    __shared__ float Xsm[16][64];   // [k][n]
    int b  = blockIdx.z;
    int n0 = blockIdx.x * 64;
    int r0 = blockIdx.y * 128;
    const float* Xb = X + (size_t)b * K * NT;
    int tid = threadIdx.x;
    int tx = tid & 15, ty = tid >> 4;   // tx: n-group (4 cols), ty: r-group (8 rows)

    float2 acc[4][4];                   // [j: n][ip: row-pair]
#pragma unroll
    for (int j = 0; j < 4; j++)
#pragma unroll
        for (int ip = 0; ip < 4; ip++) acc[j][ip] = make_float2(0.f, 0.f);

    int wr  = tid >> 1;            // 0..127 W-tile row
    int wk8 = (tid & 1) * 8;       // k offset 0 or 8
    int xk  = tid >> 4;            // 0..15  X-tile k-row
    int xj  = (tid & 15) * 4;      // n within tile

    for (int k0 = 0; k0 < K; k0 += 16) {
        __syncthreads();
        const float* wp = W + (size_t)(r0 + wr) * K + k0 + wk8;
        float4 w0 = *(const float4*)(wp);
        float4 w1 = *(const float4*)(wp + 4);
        Wsm[wk8 + 0][wr] = w0.x; Wsm[wk8 + 1][wr] = w0.y;
        Wsm[wk8 + 2][wr] = w0.z; Wsm[wk8 + 3][wr] = w0.w;
        Wsm[wk8 + 4][wr] = w1.x; Wsm[wk8 + 5][wr] = w1.y;
        Wsm[wk8 + 6][wr] = w1.z; Wsm[wk8 + 7][wr] = w1.w;
        float4 xv = *(const float4*)(Xb + (size_t)(k0 + xk) * NT + n0 + xj);
        if (mean) {
            float mu = mean[b * K + k0 + xk];
            float iv = inv [b * K + k0 + xk];
            xv.x = (xv.x - mu) * iv; xv.y = (xv.y - mu) * iv;
            xv.z = (xv.z - mu) * iv; xv.w = (xv.w - mu) * iv;
        }
        *(float4*)(&Xsm[xk][xj]) = xv;
        __syncthreads();
#pragma unroll
        for (int k = 0; k < 16; k++) {
            float4 a0 = *(const float4*)(&Wsm[k][ty * 8]);
            float4 a1 = *(const float4*)(&Wsm[k][ty * 8 + 4]);
            float2 ap[4] = {{a0.x, a0.y}, {a0.z, a0.w}, {a1.x, a1.y}, {a1.z, a1.w}};
            float4 bv = *(const float4*)(&Xsm[k][tx * 4]);
            float bb[4] = {bv.x, bv.y, bv.z, bv.w};
#pragma unroll
            for (int j = 0; j < 4; j++) {
                float2 bj = f2b(bb[j]);
#pragma unroll
                for (int ip = 0; ip < 4; ip++) ffma2(acc[j][ip], ap[ip], bj);
            }
        }
    }

    if (!transOut) {
        float* Yb = Y + (size_t)b * R * NT;
#pragma unroll
        for (int rr = 0; rr < 8; rr++) {
            int r = r0 + ty * 8 + rr;
            float bs = bias[r];
            int ip = rr >> 1;
            float4 o;
            o.x = relu6f(((rr & 1) ? acc[0][ip].y : acc[0][ip].x) + bs);
            o.y = relu6f(((rr & 1) ? acc[1][ip].y : acc[1][ip].x) + bs);
            o.z = relu6f(((rr & 1) ? acc[2][ip].y : acc[2][ip].x) + bs);
            o.w = relu6f(((rr & 1) ? acc[3][ip].y : acc[3][ip].x) + bs);
            *(float4*)(Yb + (size_t)r * NT + n0 + tx * 4) = o;
        }
    } else {
        float* Yb = Y + (size_t)b * NT * R;
        float bs[8];
#pragma unroll
        for (int rr = 0; rr < 8; rr++) bs[rr] = bias[r0 + ty * 8 + rr];
#pragma unroll
        for (int j = 0; j < 4; j++) {
            int n = n0 + tx * 4 + j;
            float4 o0, o1;
            o0.x = relu6f(acc[j][0].x + bs[0]); o0.y = relu6f(acc[j][0].y + bs[1]);
            o0.z = relu6f(acc[j][1].x + bs[2]); o0.w = relu6f(acc[j][1].y + bs[3]);
            o1.x = relu6f(acc[j][2].x + bs[4]); o1.y = relu6f(acc[j][2].y + bs[5]);
            o1.z = relu6f(acc[j][3].x + bs[6]); o1.w = relu6f(acc[j][3].y + bs[7]);
            *(float4*)(Yb + (size_t)n * R + r0 + ty * 8)     = o0;
            *(float4*)(Yb + (size_t)n * R + r0 + ty * 8 + 4) = o1;
        }
    }
}

// ---------------- fused flash attention: Fcs[b,d,n] = sum_m softmax_m(f.g) * h[d,m] ----
// BN=64 rows resident, BM=128 per iteration, 256 threads.
// S blocking: 4(n) x 8(m) per thread, PV: 4(n) x 16(d) per thread. f32x2 FMA.
__global__ __launch_bounds__(256, 1) void attn_kernel(
    const float* __restrict__ fb, const float* __restrict__ gb,
    const float* __restrict__ hTb, float* __restrict__ fcs)
{
    extern __shared__ float smbuf[];
    float* fsm = smbuf;                  // [CH][BN]   64 KB resident
    float* gsm = fsm + CH * BN;          // [KC][BM]   16 KB
    float* Psm = gsm + KC * BM;          // [BN][BM]   32 KB
    float* hsm = Psm + BN * BM;          // [64][CH]   64 KB (half-m tile)

    int b  = blockIdx.y;
    int n0 = blockIdx.x * BN;
    int tid = threadIdx.x;
    int tx = tid & 15, ty = tid >> 4;    // tx: m-group (8 cols), ty: n-group (4 rows)
    const float* f  = fb  + (size_t)b * CH * NT;
    const float* g  = gb  + (size_t)b * CH * NT;
    const float* hT = hTb + (size_t)b * NT * CH;

    // resident f tile [d][n]
    for (int e = tid; e < CH * BN / 4; e += 256) {
        int d = e >> 4, j4 = (e & 15) * 4;
        *(float4*)(fsm + d * BN + j4) = *(const float4*)(f + (size_t)d * NT + n0 + j4);
    }

    float m_i[4], l_i[4];
    float2 acc[4][8];                    // [i: n-row][d-pair]; d = dd*64 + tx*4 + pair
#pragma unroll
    for (int i = 0; i < 4; i++) {
        m_i[i] = -1e30f; l_i[i] = 0.f;
#pragma unroll
        for (int q = 0; q < 8; q++) acc[i][q] = make_float2(0.f, 0.f);
    }

    for (int mt = 0; mt < NT / BM; mt++) {
        int m0 = mt * BM;

        float2 S2[4][4];                 // [i][m-pair]: 8 m values as 4 pairs
#pragma unroll
        for (int i = 0; i < 4; i++)
#pragma unroll
            for (int jp = 0; jp < 4; jp++) S2[i][jp] = make_float2(0.f, 0.f);

        for (int kc = 0; kc < CH / KC; kc++) {
            __syncthreads();             // gsm reuse (and fsm/Psm/hsm epoch fences)
            for (int e = tid; e < KC * BM / 4; e += 256) {
                int kk = e >> 5, j4 = (e & 31) * 4;
                *(float4*)(gsm + kk * BM + j4) =
                    *(const float4*)(g + (size_t)(kc * KC + kk) * NT + m0 + j4);
            }
            __syncthreads();
#pragma unroll
            for (int k = 0; k < KC; k++) {
                float4 av = *(const float4*)(fsm + (kc * KC + k) * BN + ty * 4);
                float  a[4] = {av.x, av.y, av.z, av.w};
                float4 b0 = *(const float4*)(gsm + k * BM + tx * 8);
                float4 b1 = *(const float4*)(gsm + k * BM + tx * 8 + 4);
                float2 bp[4] = {{b0.x, b0.y}, {b0.z, b0.w}, {b1.x, b1.y}, {b1.z, b1.w}};
#pragma unroll
                for (int i = 0; i < 4; i++) {
                    float2 ai = f2b(a[i]);
#pragma unroll
                    for (int jp = 0; jp < 4; jp++) ffma2(S2[i][jp], ai, bp[jp]);
                }
            }
        }

        // online softmax; rows live on 16 tx lanes, 8 m-values each
#pragma unroll
        for (int i = 0; i < 4; i++) {
            float mx = -1e30f;
#pragma unroll
            for (int jp = 0; jp < 4; jp++) mx = fmaxf(mx, fmaxf(S2[i][jp].x, S2[i][jp].y));
#pragma unroll
            for (int o = 1; o < 16; o <<= 1) mx = fmaxf(mx, __shfl_xor_sync(0xffffffffu, mx, o));
            float mnew = fmaxf(m_i[i], mx);
            float corr = __expf(m_i[i] - mnew);
            m_i[i] = mnew;
            float p[8], rs = 0.f;
#pragma unroll
            for (int jp = 0; jp < 4; jp++) {
                p[jp * 2 + 0] = __expf(S2[i][jp].x - mnew);
                p[jp * 2 + 1] = __expf(S2[i][jp].y - mnew);
                rs += p[jp * 2] + p[jp * 2 + 1];
            }
#pragma unroll
            for (int o = 1; o < 16; o <<= 1) rs += __shfl_xor_sync(0xffffffffu, rs, o);
            l_i[i] = l_i[i] * corr + rs;
#pragma unroll
            for (int q = 0; q < 8; q++) { acc[i][q].x *= corr; acc[i][q].y *= corr; }
            *(float4*)(Psm + (ty * 4 + i) * BM + tx * 8)     = make_float4(p[0], p[1], p[2], p[3]);
            *(float4*)(Psm + (ty * 4 + i) * BM + tx * 8 + 4) = make_float4(p[4], p[5], p[6], p[7]);
        }

        // PV in two 64-m halves (hsm holds 64 x CH)
#pragma unroll
        for (int half = 0; half < 2; half++) {
            __syncthreads();             // Psm visible / hsm safe to overwrite
            for (int e = tid; e < 64 * CH / 4; e += 256) {
                int m = e >> 6, dg = (e & 63) * 4;
                *(float4*)(hsm + m * CH + dg) =
                    *(const float4*)(hT + (size_t)(m0 + half * 64 + m) * CH + dg);
            }
            __syncthreads();
#pragma unroll 2
            for (int mm = 0; mm < 64; mm++) {
                int mp = half * 64 + mm;
                float2 pb[4];
#pragma unroll
                for (int i = 0; i < 4; i++) pb[i] = f2b(Psm[(ty * 4 + i) * BM + mp]);
#pragma unroll
                for (int dd = 0; dd < 4; dd++) {
                    float4 hv = *(const float4*)(hsm + mm * CH + dd * 64 + tx * 4);
                    float2 h0 = make_float2(hv.x, hv.y);
                    float2 h1 = make_float2(hv.z, hv.w);
#pragma unroll
                    for (int i = 0; i < 4; i++) {
                        ffma2(acc[i][dd * 2 + 0], pb[i], h0);
                        ffma2(acc[i][dd * 2 + 1], pb[i], h1);
                    }
                }
            }
        }
    }

    // normalize and write Fcs[b][d][n]
    float* out = fcs + (size_t)b * CH * NT;
#pragma unroll
    for (int i = 0; i < 4; i++) {
        float invl = 1.f / l_i[i];
        int n = n0 + ty * 4 + i;
#pragma unroll
        for (int dd = 0; dd < 4; dd++) {
            int dbase = dd * 64 + tx * 4;
            out[(size_t)(dbase + 0) * NT + n] = acc[i][dd * 2 + 0].x * invl;
            out[(size_t)(dbase + 1) * NT + n] = acc[i][dd * 2 + 0].y * invl;
            out[(size_t)(dbase + 2) * NT + n] = acc[i][dd * 2 + 1].x * invl;
            out[(size_t)(dbase + 3) * NT + n] = acc[i][dd * 2 + 1].y * invl;
        }
    }
}

// ---------------- launch ----------------
extern "C" void kernel_launch(void* const* d_in, const int* in_sizes, int n_in,
                              void* d_out, int out_size) {
    const float* Fc    = (const float*)d_in[0];
    const float* Fs    = (const float*)d_in[1];
    const float* f_w   = (const float*)d_in[2];
    const float* f_b   = (const float*)d_in[3];
    const float* g_w   = (const float*)d_in[4];
    const float* g_b   = (const float*)d_in[5];
    const float* h_w   = (const float*)d_in[6];
    const float* h_b   = (const float*)d_in[7];
    const float* out_w = (const float*)d_in[8];
    const float* out_b = (const float*)d_in[9];
    float* out = (float*)d_out;

    float *pf, *pg, *phT, *pfcs, *pmean, *pinv;
    cudaGetSymbolAddress((void**)&pf,    d_f);
    cudaGetSymbolAddress((void**)&pg,    d_g);
    cudaGetSymbolAddress((void**)&phT,   d_hT);
    cudaGetSymbolAddress((void**)&pfcs,  d_fcs);
    cudaGetSymbolAddress((void**)&pmean, d_mean);
    cudaGetSymbolAddress((void**)&pinv,  d_inv);

    const size_t ATTN_SMEM =
        (size_t)(CH * BN + KC * BM + BN * BM + 64 * CH) * sizeof(float);  // 180224 B
    cudaFuncSetAttribute(attn_kernel, cudaFuncAttributeMaxDynamicSharedMemorySize,
                         (int)ATTN_SMEM);

    stats_kernel<<<dim3(BATCH * CIN, 2), 256>>>(Fc, Fs);

    // f = relu6(f_w @ mvn(Fc) + f_b)
    conv_kernel<<<dim3(NT / 64, CH / 128, BATCH), 256>>>(Fc, f_w, f_b, pmean, pinv,
                                                         pf, CH, CIN, 0);
    // g = relu6(g_w @ mvn(Fs) + g_b)
    conv_kernel<<<dim3(NT / 64, CH / 128, BATCH), 256>>>(Fs, g_w, g_b,
                                                         pmean + BATCH * CIN,
                                                         pinv  + BATCH * CIN,
                                                         pg, CH, CIN, 0);
    // h = relu6(h_w @ Fs + h_b), stored transposed [n][d]
    conv_kernel<<<dim3(NT / 64, CH / 128, BATCH), 256>>>(Fs, h_w, h_b, nullptr, nullptr,
                                                         phT, CH, CIN, 1);

    attn_kernel<<<dim3(NT / BN, BATCH), 256, ATTN_SMEM>>>(pf, pg, phT, pfcs);

    // out = relu6(out_w @ Fcs + out_b)
    conv_kernel<<<dim3(NT / 64, CIN / 128, BATCH), 256>>>(pfcs, out_w, out_b, nullptr, nullptr,
                                                          out, CIN, CH, 0);
}

// round 5
// speedup vs baseline: 2.6208x; 2.4691x over previous
#include <cuda_runtime.h>
#include <cstdint>
#include <cstddef>

#define NT    4096      // H*W tokens
#define CH    256       // hidden channels
#define CIN   512       // input channels
#define BATCH 4

// ---------------- scratch (device globals; no allocation in kernel_launch) --------
__device__ float d_fT [(size_t)BATCH * NT * CH];   // fT [b][n][d]
__device__ float d_gT [(size_t)BATCH * NT * CH];   // gT [b][m][d]
__device__ float d_h  [(size_t)BATCH * CH * NT];   // h  [b][d][m]
__device__ float d_fcs[(size_t)BATCH * CH * NT];   // Fcs[b][d][n]
__device__ float d_S  [(size_t)BATCH * NT * NT];   // scores / probs [b][n][m]
__device__ float d_mean[2 * BATCH * CIN];
__device__ float d_inv [2 * BATCH * CIN];

__device__ __forceinline__ float relu6f(float x) { return fminf(fmaxf(x, 0.0f), 6.0f); }
__device__ __forceinline__ float tf32rna(float x) {
    float r; asm("cvt.rna.tf32.f32 %0, %1;" : "=f"(r) : "f"(x)); return r;
}
// m16n8k8 tf32 MMA (baseline PTX, sm_80+; no 'a'-arch features needed)
__device__ __forceinline__ void mma8(float* d, const uint32_t* a, const uint32_t* b) {
    asm volatile("mma.sync.aligned.m16n8k8.row.col.f32.tf32.tf32.f32 "
                 "{%0,%1,%2,%3},{%4,%5,%6,%7},{%8,%9},{%0,%1,%2,%3};"
                 : "+f"(d[0]), "+f"(d[1]), "+f"(d[2]), "+f"(d[3])
                 : "r"(a[0]), "r"(a[1]), "r"(a[2]), "r"(a[3]), "r"(b[0]), "r"(b[1]));
}

// ---------------- per-(b,c) instance-norm stats, ddof=1 ----------------
__global__ __launch_bounds__(256) void stats_kernel(const float* __restrict__ Fc,
                                                    const float* __restrict__ Fs) {
    int inst  = blockIdx.x;
    int which = blockIdx.y;
    const float* src = (which ? Fs : Fc) + (size_t)inst * NT;
    int tid = threadIdx.x;
    float s = 0.f, ss = 0.f;
    for (int e = tid; e < NT / 4; e += 256) {
        float4 v = ((const float4*)src)[e];
        s  += v.x + v.y + v.z + v.w;
        ss += v.x * v.x + v.y * v.y + v.z * v.z + v.w * v.w;
    }
    for (int o = 16; o; o >>= 1) {
        s  += __shfl_xor_sync(0xffffffffu, s, o);
        ss += __shfl_xor_sync(0xffffffffu, ss, o);
    }
    __shared__ float sb[8], ssb[8];
    if ((tid & 31) == 0) { sb[tid >> 5] = s; ssb[tid >> 5] = ss; }
    __syncthreads();
    if (tid == 0) {
        s = 0.f; ss = 0.f;
        for (int w = 0; w < 8; w++) { s += sb[w]; ss += ssb[w]; }
        float mean = s / (float)NT;
        float var  = (ss - s * mean) / (float)(NT - 1);
        d_mean[which * BATCH * CIN + inst] = mean;
        d_inv [which * BATCH * CIN + inst] = rsqrtf(var + 1e-5f);
    }
}

// ---------------- 1x1-conv GEMM (scalar f32x2 path) -------
__global__ __launch_bounds__(256) void conv_kernel(
    const float* __restrict__ X, const float* __restrict__ W, const float* __restrict__ bias,
    const float* __restrict__ mean, const float* __restrict__ inv,
    float* __restrict__ Y, int R, int K, int transOut)
{
    __shared__ float Wsm[16][128];
    __shared__ float Xsm[16][64];
    int b  = blockIdx.z;
    int n0 = blockIdx.x * 64;
    int r0 = blockIdx.y * 128;
    const float* Xb = X + (size_t)b * K * NT;
    int tid = threadIdx.x;
    int tx = tid & 15, ty = tid >> 4;

    float2 acc[4][4];
#pragma unroll
    for (int j = 0; j < 4; j++)
#pragma unroll
        for (int ip = 0; ip < 4; ip++) acc[j][ip] = make_float2(0.f, 0.f);

    int wr  = tid >> 1;
    int wk8 = (tid & 1) * 8;
    int xk  = tid >> 4;
    int xj  = (tid & 15) * 4;

    for (int k0 = 0; k0 < K; k0 += 16) {
        __syncthreads();
        const float* wp = W + (size_t)(r0 + wr) * K + k0 + wk8;
        float4 w0 = *(const float4*)(wp);
        float4 w1 = *(const float4*)(wp + 4);
        Wsm[wk8 + 0][wr] = w0.x; Wsm[wk8 + 1][wr] = w0.y;
        Wsm[wk8 + 2][wr] = w0.z; Wsm[wk8 + 3][wr] = w0.w;
        Wsm[wk8 + 4][wr] = w1.x; Wsm[wk8 + 5][wr] = w1.y;
        Wsm[wk8 + 6][wr] = w1.z; Wsm[wk8 + 7][wr] = w1.w;
        float4 xv = *(const float4*)(Xb + (size_t)(k0 + xk) * NT + n0 + xj);
        if (mean) {
            float mu = mean[b * K + k0 + xk];
            float iv = inv [b * K + k0 + xk];
            xv.x = (xv.x - mu) * iv; xv.y = (xv.y - mu) * iv;
            xv.z = (xv.z - mu) * iv; xv.w = (xv.w - mu) * iv;
        }
        *(float4*)(&Xsm[xk][xj]) = xv;
        __syncthreads();
#pragma unroll
        for (int k = 0; k < 16; k++) {
            float4 a0 = *(const float4*)(&Wsm[k][ty * 8]);
            float4 a1 = *(const float4*)(&Wsm[k][ty * 8 + 4]);
            float2 ap[4] = {{a0.x, a0.y}, {a0.z, a0.w}, {a1.x, a1.y}, {a1.z, a1.w}};
            float4 bv = *(const float4*)(&Xsm[k][tx * 4]);
            float bb[4] = {bv.x, bv.y, bv.z, bv.w};
#pragma unroll
            for (int j = 0; j < 4; j++) {
                float2 bj = make_float2(bb[j], bb[j]);
#pragma unroll
                for (int ip = 0; ip < 4; ip++) {
                    asm("fma.rn.f32x2 %0, %1, %2, %0;"
                        : "+l"(*reinterpret_cast<unsigned long long*>(&acc[j][ip]))
                        : "l"(*reinterpret_cast<const unsigned long long*>(&ap[ip])),
                          "l"(*reinterpret_cast<const unsigned long long*>(&bj)));
                }
            }
        }
    }

    if (!transOut) {
        float* Yb = Y + (size_t)b * R * NT;
#pragma unroll
        for (int rr = 0; rr < 8; rr++) {
            int r = r0 + ty * 8 + rr;
            float bs = bias[r];
            int ip = rr >> 1;
            float4 o;
            o.x = relu6f(((rr & 1) ? acc[0][ip].y : acc[0][ip].x) + bs);
            o.y = relu6f(((rr & 1) ? acc[1][ip].y : acc[1][ip].x) + bs);
            o.z = relu6f(((rr & 1) ? acc[2][ip].y : acc[2][ip].x) + bs);
            o.w = relu6f(((rr & 1) ? acc[3][ip].y : acc[3][ip].x) + bs);
            *(float4*)(Yb + (size_t)r * NT + n0 + tx * 4) = o;
        }
    } else {
        float* Yb = Y + (size_t)b * NT * R;
        float bs[8];
#pragma unroll
        for (int rr = 0; rr < 8; rr++) bs[rr] = bias[r0 + ty * 8 + rr];
#pragma unroll
        for (int j = 0; j < 4; j++) {
            int n = n0 + tx * 4 + j;
            float4 o0, o1;
            o0.x = relu6f(acc[j][0].x + bs[0]); o0.y = relu6f(acc[j][0].y + bs[1]);
            o0.z = relu6f(acc[j][1].x + bs[2]); o0.w = relu6f(acc[j][1].y + bs[3]);
            o1.x = relu6f(acc[j][2].x + bs[4]); o1.y = relu6f(acc[j][2].y + bs[5]);
            o1.z = relu6f(acc[j][3].x + bs[6]); o1.w = relu6f(acc[j][3].y + bs[7]);
            *(float4*)(Yb + (size_t)n * R + r0 + ty * 8)     = o0;
            *(float4*)(Yb + (size_t)n * R + r0 + ty * 8 + 4) = o1;
        }
    }
}

// ---------------- tf32 mma.sync GEMM: C[M,N] = A[M,K] * B[N,K]^T ------------------
// CTA tile 128x128, K-chunk 32, 8 warps (warp tile 32x64), reg-prefetch pipeline.
// SPLIT=1: 3xtf32 (hi/lo) for near-fp32 accuracy (used for the score GEMM).
// SPLIT=0: single tf32, rna-rounded A operand.
// C written row-major with stride NT.
template<int SPLIT>
__global__ __launch_bounds__(256, 1)
void mma_gemm(const float* __restrict__ Ag, const float* __restrict__ Bg,
              float* __restrict__ Cg, int K, int lda, int ldb,
              size_t bA, size_t bB, size_t bC)
{
    constexpr int SROW = SPLIT ? 68 : 36;   // row stride ≡ 4 (mod 32) -> conflict-free frags
    extern __shared__ float smf[];
    float* SA = smf;
    float* SB = smf + 128 * SROW;
    const uint32_t* UA = (const uint32_t*)SA;
    const uint32_t* UB = (const uint32_t*)SB;

    const int tid  = threadIdx.x;
    const int wid  = tid >> 5, lane = tid & 31;
    const int wm   = wid & 3,  wn   = wid >> 2;   // 4 x 2 warp grid
    const int lr   = lane >> 2, lc  = lane & 3;
    const int rbase = tid >> 3;
    const int c4    = (tid & 7) * 4;

    const float* A = Ag + blockIdx.z * bA + (size_t)(blockIdx.y * 128) * lda;
    const float* B = Bg + blockIdx.z * bB + (size_t)(blockIdx.x * 128) * ldb;
    float*       C = Cg + blockIdx.z * bC + (size_t)(blockIdx.y * 128) * NT + blockIdx.x * 128;

    float acc[2][8][4];
#pragma unroll
    for (int mi = 0; mi < 2; mi++)
#pragma unroll
        for (int nj = 0; nj < 8; nj++)
#pragma unroll
            for (int q = 0; q < 4; q++) acc[mi][nj][q] = 0.f;

    float4 pa[4], pb[4];
#pragma unroll
    for (int i = 0; i < 4; i++) {
        pa[i] = *(const float4*)(A + (size_t)(rbase + 32 * i) * lda + c4);
        pb[i] = *(const float4*)(B + (size_t)(rbase + 32 * i) * ldb + c4);
    }

    const int NCH = K / 32;
    for (int c = 0; c < NCH; c++) {
#pragma unroll
        for (int i = 0; i < 4; i++) {
            int r = rbase + 32 * i;
            if (SPLIT) {
                float4 hi, lo;
                hi.x = tf32rna(pa[i].x); lo.x = pa[i].x - hi.x;
                hi.y = tf32rna(pa[i].y); lo.y = pa[i].y - hi.y;
                hi.z = tf32rna(pa[i].z); lo.z = pa[i].z - hi.z;
                hi.w = tf32rna(pa[i].w); lo.w = pa[i].w - hi.w;
                *(float4*)(SA + r * SROW + c4)      = hi;
                *(float4*)(SA + r * SROW + 32 + c4) = lo;
                hi.x = tf32rna(pb[i].x); lo.x = pb[i].x - hi.x;
                hi.y = tf32rna(pb[i].y); lo.y = pb[i].y - hi.y;
                hi.z = tf32rna(pb[i].z); lo.z = pb[i].z - hi.z;
                hi.w = tf32rna(pb[i].w); lo.w = pb[i].w - hi.w;
                *(float4*)(SB + r * SROW + c4)      = hi;
                *(float4*)(SB + r * SROW + 32 + c4) = lo;
            } else {
                float4 v = pa[i];
                v.x = tf32rna(v.x); v.y = tf32rna(v.y);
                v.z = tf32rna(v.z); v.w = tf32rna(v.w);
                *(float4*)(SA + r * SROW + c4) = v;
                *(float4*)(SB + r * SROW + c4) = pb[i];
            }
        }
        __syncthreads();
        if (c + 1 < NCH) {
#pragma unroll
            for (int i = 0; i < 4; i++) {
                pa[i] = *(const float4*)(A + (size_t)(rbase + 32 * i) * lda + (c + 1) * 32 + c4);
                pb[i] = *(const float4*)(B + (size_t)(rbase + 32 * i) * ldb + (c + 1) * 32 + c4);
            }
        }
#pragma unroll
        for (int ks = 0; ks < 4; ks++) {
            const int k0 = ks * 8;
            uint32_t ah[2][4], bh[8][2];
#pragma unroll
            for (int mi = 0; mi < 2; mi++) {
                int base = (wm * 32 + mi * 16 + lr) * SROW + k0 + lc;
                ah[mi][0] = UA[base];            ah[mi][1] = UA[base + 8 * SROW];
                ah[mi][2] = UA[base + 4];        ah[mi][3] = UA[base + 8 * SROW + 4];
            }
#pragma unroll
            for (int nj = 0; nj < 8; nj++) {
                int base = (wn * 64 + nj * 8 + lr) * SROW + k0 + lc;
                bh[nj][0] = UB[base];            bh[nj][1] = UB[base + 4];
            }
#pragma unroll
            for (int mi = 0; mi < 2; mi++)
#pragma unroll
                for (int nj = 0; nj < 8; nj++)
                    mma8(acc[mi][nj], ah[mi], bh[nj]);
            if (SPLIT) {
                uint32_t al[2][4], bl[8][2];
#pragma unroll
                for (int mi = 0; mi < 2; mi++) {
                    int base = (wm * 32 + mi * 16 + lr) * SROW + 32 + k0 + lc;
                    al[mi][0] = UA[base];        al[mi][1] = UA[base + 8 * SROW];
                    al[mi][2] = UA[base + 4];    al[mi][3] = UA[base + 8 * SROW + 4];
                }
#pragma unroll
                for (int nj = 0; nj < 8; nj++) {
                    int base = (wn * 64 + nj * 8 + lr) * SROW + 32 + k0 + lc;
                    bl[nj][0] = UB[base];        bl[nj][1] = UB[base + 4];
                }
#pragma unroll
                for (int mi = 0; mi < 2; mi++)
#pragma unroll
                    for (int nj = 0; nj < 8; nj++) {
                        mma8(acc[mi][nj], ah[mi], bl[nj]);
                        mma8(acc[mi][nj], al[mi], bh[nj]);
                    }
            }
        }
        __syncthreads();
    }

    // epilogue: direct float2 stores (lanes 0-3 cover 8 contiguous cols -> full sectors)
#pragma unroll
    for (int mi = 0; mi < 2; mi++) {
        int r = wm * 32 + mi * 16 + lr;
#pragma unroll
        for (int nj = 0; nj < 8; nj++) {
            int col = wn * 64 + nj * 8 + lc * 2;
            *(float2*)(C + (size_t)r * NT + col)       = make_float2(acc[mi][nj][0], acc[mi][nj][1]);
            *(float2*)(C + (size_t)(r + 8) * NT + col) = make_float2(acc[mi][nj][2], acc[mi][nj][3]);
        }
    }
}

// ---------------- row softmax over m (in-place on S), 4096 per row ----------------
__global__ __launch_bounds__(256) void softmax_kernel(float* __restrict__ S) {
    float* p = S + (size_t)blockIdx.x * NT;
    int tid = threadIdx.x;
    float4 v[4];
    float mx = -1e30f;
#pragma unroll
    for (int i = 0; i < 4; i++) {
        v[i] = ((const float4*)p)[tid + i * 256];
        mx = fmaxf(mx, fmaxf(fmaxf(v[i].x, v[i].y), fmaxf(v[i].z, v[i].w)));
    }
    __shared__ float redm[8], reds[8];
#pragma unroll
    for (int o = 16; o; o >>= 1) mx = fmaxf(mx, __shfl_xor_sync(0xffffffffu, mx, o));
    if ((tid & 31) == 0) redm[tid >> 5] = mx;
    __syncthreads();
    mx = fmaxf(fmaxf(fmaxf(redm[0], redm[1]), fmaxf(redm[2], redm[3])),
               fmaxf(fmaxf(redm[4], redm[5]), fmaxf(redm[6], redm[7])));
    float s = 0.f;
#pragma unroll
    for (int i = 0; i < 4; i++) {
        v[i].x = __expf(v[i].x - mx); v[i].y = __expf(v[i].y - mx);
        v[i].z = __expf(v[i].z - mx); v[i].w = __expf(v[i].w - mx);
        s += v[i].x + v[i].y + v[i].z + v[i].w;
    }
#pragma unroll
    for (int o = 16; o; o >>= 1) s += __shfl_xor_sync(0xffffffffu, s, o);
    if ((tid & 31) == 0) reds[tid >> 5] = s;
    __syncthreads();
    s = reds[0] + reds[1] + reds[2] + reds[3] + reds[4] + reds[5] + reds[6] + reds[7];
    float inv = 1.f / s;
#pragma unroll
    for (int i = 0; i < 4; i++) {
        v[i].x *= inv; v[i].y *= inv; v[i].z *= inv; v[i].w *= inv;
        ((float4*)p)[tid + i * 256] = v[i];
    }
}

// ---------------- launch ----------------
extern "C" void kernel_launch(void* const* d_in, const int* in_sizes, int n_in,
                              void* d_out, int out_size) {
    const float* Fc    = (const float*)d_in[0];
    const float* Fs    = (const float*)d_in[1];
    const float* f_w   = (const float*)d_in[2];
    const float* f_b   = (const float*)d_in[3];
    const float* g_w   = (const float*)d_in[4];
    const float* g_b   = (const float*)d_in[5];
    const float* h_w   = (const float*)d_in[6];
    const float* h_b   = (const float*)d_in[7];
    const float* out_w = (const float*)d_in[8];
    const float* out_b = (const float*)d_in[9];
    float* out = (float*)d_out;

    float *pfT, *pgT, *ph, *pfcs, *pS, *pmean, *pinv;
    cudaGetSymbolAddress((void**)&pfT,   d_fT);
    cudaGetSymbolAddress((void**)&pgT,   d_gT);
    cudaGetSymbolAddress((void**)&ph,    d_h);
    cudaGetSymbolAddress((void**)&pfcs,  d_fcs);
    cudaGetSymbolAddress((void**)&pS,    d_S);
    cudaGetSymbolAddress((void**)&pmean, d_mean);
    cudaGetSymbolAddress((void**)&pinv,  d_inv);

    const int SMEM1 = 2 * 128 * 68 * 4;   // 69632 B (split)
    const int SMEM2 = 2 * 128 * 36 * 4;   // 36864 B
    cudaFuncSetAttribute(mma_gemm<1>, cudaFuncAttributeMaxDynamicSharedMemorySize, SMEM1);
    cudaFuncSetAttribute(mma_gemm<0>, cudaFuncAttributeMaxDynamicSharedMemorySize, SMEM2);

    stats_kernel<<<dim3(BATCH * CIN, 2), 256>>>(Fc, Fs);

    // fT[n][d] = relu6(f_w @ mvn(Fc) + f_b)^T ; gT[m][d] likewise ; h[d][m] direct
    conv_kernel<<<dim3(NT / 64, CH / 128, BATCH), 256>>>(Fc, f_w, f_b, pmean, pinv,
                                                         pfT, CH, CIN, 1);
    conv_kernel<<<dim3(NT / 64, CH / 128, BATCH), 256>>>(Fs, g_w, g_b,
                                                         pmean + BATCH * CIN,
                                                         pinv  + BATCH * CIN,
                                                         pgT, CH, CIN, 1);
    conv_kernel<<<dim3(NT / 64, CH / 128, BATCH), 256>>>(Fs, h_w, h_b, nullptr, nullptr,
                                                         ph, CH, CIN, 0);

    // S[n][m] = fT . gT^T   (3xtf32 mma.sync)
    mma_gemm<1><<<dim3(NT / 128, NT / 128, BATCH), 256, SMEM1>>>(
        pfT, pgT, pS, CH, CH, CH,
        (size_t)NT * CH, (size_t)NT * CH, (size_t)NT * NT);

    // P = softmax_m(S), in place
    softmax_kernel<<<BATCH * NT, 256>>>(pS);

    // fcs[d][n] = h . P^T   (tf32 mma.sync)
    mma_gemm<0><<<dim3(NT / 128, CH / 128, BATCH), 256, SMEM2>>>(
        ph, pS, pfcs, NT, NT, NT,
        (size_t)CH * NT, (size_t)NT * NT, (size_t)CH * NT);

    // out = relu6(out_w @ Fcs + out_b)
    conv_kernel<<<dim3(NT / 64, CIN / 128, BATCH), 256>>>(pfcs, out_w, out_b, nullptr, nullptr,
                                                          out, CIN, CH, 0);
}

// round 6
// speedup vs baseline: 2.9738x; 1.1347x over previous
#include <cuda_runtime.h>
#include <cstdint>
#include <cstddef>

#define NT    4096      // H*W tokens
#define CH    256       // hidden channels
#define CIN   512       // input channels
#define BATCH 4

// ---------------- scratch (device globals; no allocation in kernel_launch) --------
__device__ float d_fT [(size_t)BATCH * NT * CH];   // fT [b][n][d]
__device__ float d_gT [(size_t)BATCH * NT * CH];   // gT [b][m][d]
__device__ float d_h  [(size_t)BATCH * CH * NT];   // h  [b][d][m]
__device__ float d_fcs[(size_t)BATCH * NT * CH];   // Fcs[b][n][d]
__device__ float d_S  [(size_t)BATCH * NT * NT];   // scores / probs [b][n][m]
__device__ float d_mean[2 * BATCH * CIN];
__device__ float d_inv [2 * BATCH * CIN];

__device__ __forceinline__ float relu6f(float x) { return fminf(fmaxf(x, 0.0f), 6.0f); }
__device__ __forceinline__ float tf32rna(float x) {
    float r; asm("cvt.rna.tf32.f32 %0, %1;" : "=f"(r) : "f"(x)); return r;
}
// m16n8k8 tf32 MMA (baseline PTX, sm_80+)
__device__ __forceinline__ void mma8(float* d, const uint32_t* a, const uint32_t* b) {
    asm volatile("mma.sync.aligned.m16n8k8.row.col.f32.tf32.tf32.f32 "
                 "{%0,%1,%2,%3},{%4,%5,%6,%7},{%8,%9},{%0,%1,%2,%3};"
                 : "+f"(d[0]), "+f"(d[1]), "+f"(d[2]), "+f"(d[3])
                 : "r"(a[0]), "r"(a[1]), "r"(a[2]), "r"(a[3]), "r"(b[0]), "r"(b[1]));
}

// ---------------- per-(b,c) instance-norm stats, ddof=1 ----------------
__global__ __launch_bounds__(256) void stats_kernel(const float* __restrict__ Fc,
                                                    const float* __restrict__ Fs) {
    int inst  = blockIdx.x;
    int which = blockIdx.y;
    const float* src = (which ? Fs : Fc) + (size_t)inst * NT;
    int tid = threadIdx.x;
    float s = 0.f, ss = 0.f;
    for (int e = tid; e < NT / 4; e += 256) {
        float4 v = ((const float4*)src)[e];
        s  += v.x + v.y + v.z + v.w;
        ss += v.x * v.x + v.y * v.y + v.z * v.z + v.w * v.w;
    }
    for (int o = 16; o; o >>= 1) {
        s  += __shfl_xor_sync(0xffffffffu, s, o);
        ss += __shfl_xor_sync(0xffffffffu, ss, o);
    }
    __shared__ float sb[8], ssb[8];
    if ((tid & 31) == 0) { sb[tid >> 5] = s; ssb[tid >> 5] = ss; }
    __syncthreads();
    if (tid == 0) {
        s = 0.f; ss = 0.f;
        for (int w = 0; w < 8; w++) { s += sb[w]; ss += ssb[w]; }
        float mean = s / (float)NT;
        float var  = (ss - s * mean) / (float)(NT - 1);
        d_mean[which * BATCH * CIN + inst] = mean;
        d_inv [which * BATCH * CIN + inst] = rsqrtf(var + 1e-5f);
    }
}

// ---------------- tf32 mma.sync GEMM: C[M,N] = A[M,K] * B[N,K]^T (+bias, relu6) ---
// CTA tile 128x128, K-chunk 32, 8 warps (32x64 warp tile), reg-prefetch pipeline.
template<int SPLIT, int ACT>
__global__ __launch_bounds__(256, 1)
void mma_gemm(const float* __restrict__ Ag, const float* __restrict__ Bg,
              const float* __restrict__ bias, float* __restrict__ Cg,
              int K, int lda, int ldb, int ldc,
              size_t bA, size_t bB, size_t bC)
{
    constexpr int SROW = SPLIT ? 68 : 36;   // ≡4 mod 32 -> conflict-free fragment reads
    extern __shared__ float smf[];
    float* SA = smf;
    float* SB = smf + 128 * SROW;
    const uint32_t* UA = (const uint32_t*)SA;
    const uint32_t* UB = (const uint32_t*)SB;

    const int tid  = threadIdx.x;
    const int wid  = tid >> 5, lane = tid & 31;
    const int wm   = wid & 3,  wn   = wid >> 2;
    const int lr   = lane >> 2, lc  = lane & 3;
    const int rbase = tid >> 3;
    const int c4    = (tid & 7) * 4;

    const float* A = Ag + blockIdx.z * bA + (size_t)(blockIdx.y * 128) * lda;
    const float* B = Bg + blockIdx.z * bB + (size_t)(blockIdx.x * 128) * ldb;
    float*       C = Cg + blockIdx.z * bC + (size_t)(blockIdx.y * 128) * ldc + blockIdx.x * 128;

    float acc[2][8][4];
#pragma unroll
    for (int mi = 0; mi < 2; mi++)
#pragma unroll
        for (int nj = 0; nj < 8; nj++)
#pragma unroll
            for (int q = 0; q < 4; q++) acc[mi][nj][q] = 0.f;

    float4 pa[4], pb[4];
#pragma unroll
    for (int i = 0; i < 4; i++) {
        pa[i] = *(const float4*)(A + (size_t)(rbase + 32 * i) * lda + c4);
        pb[i] = *(const float4*)(B + (size_t)(rbase + 32 * i) * ldb + c4);
    }

    const int NCH = K / 32;
    for (int c = 0; c < NCH; c++) {
#pragma unroll
        for (int i = 0; i < 4; i++) {
            int r = rbase + 32 * i;
            if (SPLIT) {
                float4 hi, lo;
                hi.x = tf32rna(pa[i].x); lo.x = pa[i].x - hi.x;
                hi.y = tf32rna(pa[i].y); lo.y = pa[i].y - hi.y;
                hi.z = tf32rna(pa[i].z); lo.z = pa[i].z - hi.z;
                hi.w = tf32rna(pa[i].w); lo.w = pa[i].w - hi.w;
                *(float4*)(SA + r * SROW + c4)      = hi;
                *(float4*)(SA + r * SROW + 32 + c4) = lo;
                hi.x = tf32rna(pb[i].x); lo.x = pb[i].x - hi.x;
                hi.y = tf32rna(pb[i].y); lo.y = pb[i].y - hi.y;
                hi.z = tf32rna(pb[i].z); lo.z = pb[i].z - hi.z;
                hi.w = tf32rna(pb[i].w); lo.w = pb[i].w - hi.w;
                *(float4*)(SB + r * SROW + c4)      = hi;
                *(float4*)(SB + r * SROW + 32 + c4) = lo;
            } else {
                float4 v = pa[i];
                v.x = tf32rna(v.x); v.y = tf32rna(v.y);
                v.z = tf32rna(v.z); v.w = tf32rna(v.w);
                *(float4*)(SA + r * SROW + c4) = v;
                v = pb[i];
                v.x = tf32rna(v.x); v.y = tf32rna(v.y);
                v.z = tf32rna(v.z); v.w = tf32rna(v.w);
                *(float4*)(SB + r * SROW + c4) = v;
            }
        }
        __syncthreads();
        if (c + 1 < NCH) {
#pragma unroll
            for (int i = 0; i < 4; i++) {
                pa[i] = *(const float4*)(A + (size_t)(rbase + 32 * i) * lda + (c + 1) * 32 + c4);
                pb[i] = *(const float4*)(B + (size_t)(rbase + 32 * i) * ldb + (c + 1) * 32 + c4);
            }
        }
#pragma unroll
        for (int ks = 0; ks < 4; ks++) {
            const int k0 = ks * 8;
            uint32_t ah[2][4], bh[8][2];
#pragma unroll
            for (int mi = 0; mi < 2; mi++) {
                int base = (wm * 32 + mi * 16 + lr) * SROW + k0 + lc;
                ah[mi][0] = UA[base];            ah[mi][1] = UA[base + 8 * SROW];
                ah[mi][2] = UA[base + 4];        ah[mi][3] = UA[base + 8 * SROW + 4];
            }
#pragma unroll
            for (int nj = 0; nj < 8; nj++) {
                int base = (wn * 64 + nj * 8 + lr) * SROW + k0 + lc;
                bh[nj][0] = UB[base];            bh[nj][1] = UB[base + 4];
            }
#pragma unroll
            for (int mi = 0; mi < 2; mi++)
#pragma unroll
                for (int nj = 0; nj < 8; nj++)
                    mma8(acc[mi][nj], ah[mi], bh[nj]);
            if (SPLIT) {
                uint32_t al[2][4], bl[8][2];
#pragma unroll
                for (int mi = 0; mi < 2; mi++) {
                    int base = (wm * 32 + mi * 16 + lr) * SROW + 32 + k0 + lc;
                    al[mi][0] = UA[base];        al[mi][1] = UA[base + 8 * SROW];
                    al[mi][2] = UA[base + 4];    al[mi][3] = UA[base + 8 * SROW + 4];
                }
#pragma unroll
                for (int nj = 0; nj < 8; nj++) {
                    int base = (wn * 64 + nj * 8 + lr) * SROW + 32 + k0 + lc;
                    bl[nj][0] = UB[base];        bl[nj][1] = UB[base + 4];
                }
#pragma unroll
                for (int mi = 0; mi < 2; mi++)
#pragma unroll
                    for (int nj = 0; nj < 8; nj++) {
                        mma8(acc[mi][nj], ah[mi], bl[nj]);
                        mma8(acc[mi][nj], al[mi], bh[nj]);
                    }
            }
        }
        __syncthreads();
    }

#pragma unroll
    for (int mi = 0; mi < 2; mi++) {
        int r = wm * 32 + mi * 16 + lr;
        float b0 = 0.f, b1 = 0.f;
        if (ACT) {
            b0 = bias[blockIdx.y * 128 + r];
            b1 = bias[blockIdx.y * 128 + r + 8];
        }
#pragma unroll
        for (int nj = 0; nj < 8; nj++) {
            int col = wn * 64 + nj * 8 + lc * 2;
            float2 v0 = make_float2(acc[mi][nj][0], acc[mi][nj][1]);
            float2 v1 = make_float2(acc[mi][nj][2], acc[mi][nj][3]);
            if (ACT) {
                v0.x = relu6f(v0.x + b0); v0.y = relu6f(v0.y + b0);
                v1.x = relu6f(v1.x + b1); v1.y = relu6f(v1.y + b1);
            }
            *(float2*)(C + (size_t)r * ldc + col)       = v0;
            *(float2*)(C + (size_t)(r + 8) * ldc + col) = v1;
        }
    }
}

// ---------------- tensor-core 1x1 conv: C = relu6(W @ X + bias) -------------------
// A = W[r][k] row-major; B = X[k][n] (k-major gmem) read via [k][n] smem tile.
// Optional instance-norm of X. TRANSOUT=1 -> write C[n][r] (smem-staged transpose).
template<int SPLIT, int TRANSOUT>
__global__ __launch_bounds__(256, 1)
void conv_mma(const float* __restrict__ Wg, const float* __restrict__ Xg,
              const float* __restrict__ bias,
              const float* __restrict__ mean, const float* __restrict__ inv,
              float* __restrict__ Cg, int K, int ldc, size_t bC)
{
    constexpr int SROW = SPLIT ? 68 : 36;
    extern __shared__ float smf[];
    float* SA  = smf;                              // W tile [128r][SROW]
    float* XS0 = smf + 128 * SROW;                 // X tile hi [32k][132]
    float* XS1 = XS0 + (SPLIT ? 32 * 132 : 0);     // X tile lo
    float* stage = smf;                            // epilogue overlay [128n][132]
    const uint32_t* UA  = (const uint32_t*)SA;
    const uint32_t* UX0 = (const uint32_t*)XS0;
    const uint32_t* UX1 = (const uint32_t*)XS1;

    const int tid  = threadIdx.x;
    const int wid  = tid >> 5, lane = tid & 31;
    const int wm   = wid & 3,  wn   = wid >> 4 ? 1 : (wid >> 2);  // placeholder fix below
    const int wn2  = wid >> 2;
    const int lr   = lane >> 2, lc  = lane & 3;
    const int rbase = tid >> 3;
    const int c4    = (tid & 7) * 4;
    const int kk    = tid >> 5;          // 0..7 (k row group for X loads)
    const int n4    = (tid & 31) * 4;

    const int b  = blockIdx.z;
    const int n0 = blockIdx.x * 128;
    const int r0 = blockIdx.y * 128;
    const float* X = Xg + (size_t)b * K * NT;
    const float* mu = mean ? mean + b * K : nullptr;
    const float* iv = inv  ? inv  + b * K : nullptr;
    float* C = Cg + b * bC;

    float acc[2][8][4];
#pragma unroll
    for (int mi = 0; mi < 2; mi++)
#pragma unroll
        for (int nj = 0; nj < 8; nj++)
#pragma unroll
            for (int q = 0; q < 4; q++) acc[mi][nj][q] = 0.f;

    float4 pa[4], px[4];
    float pm[4], pv[4];
#pragma unroll
    for (int i = 0; i < 4; i++) {
        pa[i] = *(const float4*)(Wg + (size_t)(r0 + rbase + 32 * i) * K + c4);
        int k = kk + 8 * i;
        px[i] = *(const float4*)(X + (size_t)k * NT + n0 + n4);
        pm[i] = mu ? mu[k] : 0.f;
        pv[i] = iv ? iv[k] : 1.f;
    }

    const int NCH = K / 32;
    for (int c = 0; c < NCH; c++) {
        // store W tile
#pragma unroll
        for (int i = 0; i < 4; i++) {
            int r = rbase + 32 * i;
            if (SPLIT) {
                float4 hi, lo;
                hi.x = tf32rna(pa[i].x); lo.x = pa[i].x - hi.x;
                hi.y = tf32rna(pa[i].y); lo.y = pa[i].y - hi.y;
                hi.z = tf32rna(pa[i].z); lo.z = pa[i].z - hi.z;
                hi.w = tf32rna(pa[i].w); lo.w = pa[i].w - hi.w;
                *(float4*)(SA + r * SROW + c4)      = hi;
                *(float4*)(SA + r * SROW + 32 + c4) = lo;
            } else {
                float4 v = pa[i];
                v.x = tf32rna(v.x); v.y = tf32rna(v.y);
                v.z = tf32rna(v.z); v.w = tf32rna(v.w);
                *(float4*)(SA + r * SROW + c4) = v;
            }
        }
        // store X tile (normalized), [k][n] layout
#pragma unroll
        for (int i = 0; i < 4; i++) {
            int k = kk + 8 * i;
            float4 v = px[i];
            v.x = (v.x - pm[i]) * pv[i]; v.y = (v.y - pm[i]) * pv[i];
            v.z = (v.z - pm[i]) * pv[i]; v.w = (v.w - pm[i]) * pv[i];
            if (SPLIT) {
                float4 hi, lo;
                hi.x = tf32rna(v.x); lo.x = v.x - hi.x;
                hi.y = tf32rna(v.y); lo.y = v.y - hi.y;
                hi.z = tf32rna(v.z); lo.z = v.z - hi.z;
                hi.w = tf32rna(v.w); lo.w = v.w - hi.w;
                *(float4*)(XS0 + k * 132 + n4) = hi;
                *(float4*)(XS1 + k * 132 + n4) = lo;
            } else {
                v.x = tf32rna(v.x); v.y = tf32rna(v.y);
                v.z = tf32rna(v.z); v.w = tf32rna(v.w);
                *(float4*)(XS0 + k * 132 + n4) = v;
            }
        }
        __syncthreads();
        if (c + 1 < NCH) {
#pragma unroll
            for (int i = 0; i < 4; i++) {
                pa[i] = *(const float4*)(Wg + (size_t)(r0 + rbase + 32 * i) * K + (c + 1) * 32 + c4);
                int k = (c + 1) * 32 + kk + 8 * i;
                px[i] = *(const float4*)(X + (size_t)k * NT + n0 + n4);
                pm[i] = mu ? mu[k] : 0.f;
                pv[i] = iv ? iv[k] : 1.f;
            }
        }
#pragma unroll
        for (int ks = 0; ks < 4; ks++) {
            const int k0 = ks * 8;
            uint32_t ah[2][4], bh[8][2];
#pragma unroll
            for (int mi = 0; mi < 2; mi++) {
                int base = (wm * 32 + mi * 16 + lr) * SROW + k0 + lc;
                ah[mi][0] = UA[base];            ah[mi][1] = UA[base + 8 * SROW];
                ah[mi][2] = UA[base + 4];        ah[mi][3] = UA[base + 8 * SROW + 4];
            }
#pragma unroll
            for (int nj = 0; nj < 8; nj++) {
                int col = wn2 * 64 + nj * 8 + lr;
                bh[nj][0] = UX0[(k0 + lc) * 132 + col];
                bh[nj][1] = UX0[(k0 + lc + 4) * 132 + col];
            }
#pragma unroll
            for (int mi = 0; mi < 2; mi++)
#pragma unroll
                for (int nj = 0; nj < 8; nj++)
                    mma8(acc[mi][nj], ah[mi], bh[nj]);
            if (SPLIT) {
                uint32_t al[2][4], bl[8][2];
#pragma unroll
                for (int mi = 0; mi < 2; mi++) {
                    int base = (wm * 32 + mi * 16 + lr) * SROW + 32 + k0 + lc;
                    al[mi][0] = UA[base];        al[mi][1] = UA[base + 8 * SROW];
                    al[mi][2] = UA[base + 4];    al[mi][3] = UA[base + 8 * SROW + 4];
                }
#pragma unroll
                for (int nj = 0; nj < 8; nj++) {
                    int col = wn2 * 64 + nj * 8 + lr;
                    bl[nj][0] = UX1[(k0 + lc) * 132 + col];
                    bl[nj][1] = UX1[(k0 + lc + 4) * 132 + col];
                }
#pragma unroll
                for (int mi = 0; mi < 2; mi++)
#pragma unroll
                    for (int nj = 0; nj < 8; nj++) {
                        mma8(acc[mi][nj], ah[mi], bl[nj]);
                        mma8(acc[mi][nj], al[mi], bh[nj]);
                    }
            }
        }
        __syncthreads();
    }

    if (!TRANSOUT) {
        // C[r][n], ldc = NT
#pragma unroll
        for (int mi = 0; mi < 2; mi++) {
            int r = wm * 32 + mi * 16 + lr;
            float b0 = bias[r0 + r], b1 = bias[r0 + r + 8];
#pragma unroll
            for (int nj = 0; nj < 8; nj++) {
                int col = wn2 * 64 + nj * 8 + lc * 2;
                float2 v0 = make_float2(relu6f(acc[mi][nj][0] + b0),
                                        relu6f(acc[mi][nj][1] + b0));
                float2 v1 = make_float2(relu6f(acc[mi][nj][2] + b1),
                                        relu6f(acc[mi][nj][3] + b1));
                *(float2*)(C + (size_t)(r0 + r) * ldc + n0 + col)     = v0;
                *(float2*)(C + (size_t)(r0 + r + 8) * ldc + n0 + col) = v1;
            }
        }
    } else {
        // stage transposed, then write C[n][r], ldc = R
#pragma unroll
        for (int mi = 0; mi < 2; mi++) {
            int r = wm * 32 + mi * 16 + lr;
            float b0 = bias[r0 + r], b1 = bias[r0 + r + 8];
#pragma unroll
            for (int nj = 0; nj < 8; nj++) {
                int nl = wn2 * 64 + nj * 8 + lc * 2;
                stage[(size_t)nl * 132 + r]           = relu6f(acc[mi][nj][0] + b0);
                stage[(size_t)(nl + 1) * 132 + r]     = relu6f(acc[mi][nj][1] + b0);
                stage[(size_t)nl * 132 + r + 8]       = relu6f(acc[mi][nj][2] + b1);
                stage[(size_t)(nl + 1) * 132 + r + 8] = relu6f(acc[mi][nj][3] + b1);
            }
        }
        __syncthreads();
#pragma unroll
        for (int i = 0; i < 16; i++) {
            int e = tid + i * 256;
            int n = e >> 5, r4 = (e & 31) * 4;
            *(float4*)(C + (size_t)(n0 + n) * ldc + r0 + r4) = *(const float4*)(stage + n * 132 + r4);
        }
    }
}

// ---------------- row softmax over m (in-place on S), 4096 per row ----------------
__global__ __launch_bounds__(256) void softmax_kernel(float* __restrict__ S) {
    float* p = S + (size_t)blockIdx.x * NT;
    int tid = threadIdx.x;
    float4 v[4];
    float mx = -1e30f;
#pragma unroll
    for (int i = 0; i < 4; i++) {
        v[i] = ((const float4*)p)[tid + i * 256];
        mx = fmaxf(mx, fmaxf(fmaxf(v[i].x, v[i].y), fmaxf(v[i].z, v[i].w)));
    }
    __shared__ float redm[8], reds[8];
#pragma unroll
    for (int o = 16; o; o >>= 1) mx = fmaxf(mx, __shfl_xor_sync(0xffffffffu, mx, o));
    if ((tid & 31) == 0) redm[tid >> 5] = mx;
    __syncthreads();
    mx = fmaxf(fmaxf(fmaxf(redm[0], redm[1]), fmaxf(redm[2], redm[3])),
               fmaxf(fmaxf(redm[4], redm[5]), fmaxf(redm[6], redm[7])));
    float s = 0.f;
#pragma unroll
    for (int i = 0; i < 4; i++) {
        v[i].x = __expf(v[i].x - mx); v[i].y = __expf(v[i].y - mx);
        v[i].z = __expf(v[i].z - mx); v[i].w = __expf(v[i].w - mx);
        s += v[i].x + v[i].y + v[i].z + v[i].w;
    }
#pragma unroll
    for (int o = 16; o; o >>= 1) s += __shfl_xor_sync(0xffffffffu, s, o);
    if ((tid & 31) == 0) reds[tid >> 5] = s;
    __syncthreads();
    s = reds[0] + reds[1] + reds[2] + reds[3] + reds[4] + reds[5] + reds[6] + reds[7];
    float inv = 1.f / s;
#pragma unroll
    for (int i = 0; i < 4; i++) {
        v[i].x *= inv; v[i].y *= inv; v[i].z *= inv; v[i].w *= inv;
        ((float4*)p)[tid + i * 256] = v[i];
    }
}

// ---------------- launch ----------------
extern "C" void kernel_launch(void* const* d_in, const int* in_sizes, int n_in,
                              void* d_out, int out_size) {
    const float* Fc    = (const float*)d_in[0];
    const float* Fs    = (const float*)d_in[1];
    const float* f_w   = (const float*)d_in[2];
    const float* f_b   = (const float*)d_in[3];
    const float* g_w   = (const float*)d_in[4];
    const float* g_b   = (const float*)d_in[5];
    const float* h_w   = (const float*)d_in[6];
    const float* h_b   = (const float*)d_in[7];
    const float* out_w = (const float*)d_in[8];
    const float* out_b = (const float*)d_in[9];
    float* out = (float*)d_out;

    float *pfT, *pgT, *ph, *pfcs, *pS, *pmean, *pinv;
    cudaGetSymbolAddress((void**)&pfT,   d_fT);
    cudaGetSymbolAddress((void**)&pgT,   d_gT);
    cudaGetSymbolAddress((void**)&ph,    d_h);
    cudaGetSymbolAddress((void**)&pfcs,  d_fcs);
    cudaGetSymbolAddress((void**)&pS,    d_S);
    cudaGetSymbolAddress((void**)&pmean, d_mean);
    cudaGetSymbolAddress((void**)&pinv,  d_inv);

    const int SM_G1 = 2 * 128 * 68 * 4;                 // 69632 (split gemm)
    const int SM_G0 = 2 * 128 * 36 * 4;                 // 36864
    const int SM_C1 = (128 * 68 + 2 * 32 * 132) * 4;    // 68608 (split conv, >= stage 67584)
    const int SM_C0 = (128 * 36 + 32 * 132) * 4;        // 35328
    cudaFuncSetAttribute(mma_gemm<1, 0>, cudaFuncAttributeMaxDynamicSharedMemorySize, SM_G1);
    cudaFuncSetAttribute(mma_gemm<0, 0>, cudaFuncAttributeMaxDynamicSharedMemorySize, SM_G0);
    cudaFuncSetAttribute(mma_gemm<0, 1>, cudaFuncAttributeMaxDynamicSharedMemorySize, SM_G0);
    cudaFuncSetAttribute(conv_mma<1, 1>, cudaFuncAttributeMaxDynamicSharedMemorySize, SM_C1);
    cudaFuncSetAttribute(conv_mma<0, 0>, cudaFuncAttributeMaxDynamicSharedMemorySize, SM_C0);

    stats_kernel<<<dim3(BATCH * CIN, 2), 256>>>(Fc, Fs);

    // fT[n][d] = relu6(f_w @ mvn(Fc) + f_b)^T   (3xtf32)
    conv_mma<1, 1><<<dim3(NT / 128, CH / 128, BATCH), 256, SM_C1>>>(
        f_w, Fc, f_b, pmean, pinv, pfT, CIN, CH, (size_t)NT * CH);
    // gT[m][d] = relu6(g_w @ mvn(Fs) + g_b)^T   (3xtf32)
    conv_mma<1, 1><<<dim3(NT / 128, CH / 128, BATCH), 256, SM_C1>>>(
        g_w, Fs, g_b, pmean + BATCH * CIN, pinv + BATCH * CIN, pgT, CIN, CH, (size_t)NT * CH);
    // h[d][m] = relu6(h_w @ Fs + h_b)           (1xtf32)
    conv_mma<0, 0><<<dim3(NT / 128, CH / 128, BATCH), 256, SM_C0>>>(
        h_w, Fs, h_b, nullptr, nullptr, ph, CIN, NT, (size_t)CH * NT);

    // S[n][m] = fT . gT^T   (3xtf32)
    mma_gemm<1, 0><<<dim3(NT / 128, NT / 128, BATCH), 256, SM_G1>>>(
        pfT, pgT, nullptr, pS, CH, CH, CH, NT,
        (size_t)NT * CH, (size_t)NT * CH, (size_t)NT * NT);

    // P = softmax_m(S), in place
    softmax_kernel<<<BATCH * NT, 256>>>(pS);

    // fcs[n][d] = P . h^T   (1xtf32)
    mma_gemm<0, 0><<<dim3(CH / 128, NT / 128, BATCH), 256, SM_G0>>>(
        pS, ph, nullptr, pfcs, NT, NT, NT, CH,
        (size_t)NT * NT, (size_t)CH * NT, (size_t)NT * CH);

    // out[r][n] = relu6(out_w @ fcs^T + out_b)  (1xtf32)
    mma_gemm<0, 1><<<dim3(NT / 128, CIN / 128, BATCH), 256, SM_G0>>>(
        out_w, pfcs, out_b, out, CH, CH, CH, NT,
        (size_t)0, (size_t)NT * CH, (size_t)CIN * NT);
}

// round 7
// speedup vs baseline: 2.9773x; 1.0012x over previous
#include <cuda_runtime.h>
#include <cstdint>
#include <cstddef>

#define NT    4096      // H*W tokens
#define CH    256       // hidden channels
#define CIN   512       // input channels
#define BATCH 4

// ---------------- scratch (device globals; no allocation in kernel_launch) --------
__device__ float d_fT [(size_t)BATCH * NT * CH];   // fT [b][n][d]
__device__ float d_gT [(size_t)BATCH * NT * CH];   // gT [b][m][d]
__device__ float d_h  [(size_t)BATCH * CH * NT];   // h  [b][d][m]
__device__ float d_fcs[(size_t)BATCH * NT * CH];   // Fcs[b][n][d]
__device__ float d_S  [(size_t)BATCH * NT * NT];   // scores / probs [b][n][m]
__device__ float d_mean[2 * BATCH * CIN];
__device__ float d_inv [2 * BATCH * CIN];

__device__ __forceinline__ float relu6f(float x) { return fminf(fmaxf(x, 0.0f), 6.0f); }
__device__ __forceinline__ float tf32rna(float x) {
    float r; asm("cvt.rna.tf32.f32 %0, %1;" : "=f"(r) : "f"(x)); return r;
}
// m16n8k8 tf32 MMA (baseline PTX, sm_80+)
__device__ __forceinline__ void mma8(float* d, const uint32_t* a, const uint32_t* b) {
    asm volatile("mma.sync.aligned.m16n8k8.row.col.f32.tf32.tf32.f32 "
                 "{%0,%1,%2,%3},{%4,%5,%6,%7},{%8,%9},{%0,%1,%2,%3};"
                 : "+f"(d[0]), "+f"(d[1]), "+f"(d[2]), "+f"(d[3])
                 : "r"(a[0]), "r"(a[1]), "r"(a[2]), "r"(a[3]), "r"(b[0]), "r"(b[1]));
}

// ---------------- per-(b,c) instance-norm stats, ddof=1 ----------------
__global__ __launch_bounds__(256) void stats_kernel(const float* __restrict__ Fc,
                                                    const float* __restrict__ Fs) {
    int inst  = blockIdx.x;
    int which = blockIdx.y;
    const float* src = (which ? Fs : Fc) + (size_t)inst * NT;
    int tid = threadIdx.x;
    float s = 0.f, ss = 0.f;
    for (int e = tid; e < NT / 4; e += 256) {
        float4 v = ((const float4*)src)[e];
        s  += v.x + v.y + v.z + v.w;
        ss += v.x * v.x + v.y * v.y + v.z * v.z + v.w * v.w;
    }
    for (int o = 16; o; o >>= 1) {
        s  += __shfl_xor_sync(0xffffffffu, s, o);
        ss += __shfl_xor_sync(0xffffffffu, ss, o);
    }
    __shared__ float sb[8], ssb[8];
    if ((tid & 31) == 0) { sb[tid >> 5] = s; ssb[tid >> 5] = ss; }
    __syncthreads();
    if (tid == 0) {
        s = 0.f; ss = 0.f;
        for (int w = 0; w < 8; w++) { s += sb[w]; ss += ssb[w]; }
        float mean = s / (float)NT;
        float var  = (ss - s * mean) / (float)(NT - 1);
        d_mean[which * BATCH * CIN + inst] = mean;
        d_inv [which * BATCH * CIN + inst] = rsqrtf(var + 1e-5f);
    }
}

// ---------------- tf32 mma.sync GEMM: C[M,N] = A[M,K] * B[N,K]^T (+bias, relu6) ---
// CTA tile 128x128, K-chunk 32, 8 warps (32x64 warp tile), reg-prefetch pipeline.
template<int SPLIT, int ACT>
__global__ __launch_bounds__(256, 1)
void mma_gemm(const float* __restrict__ Ag, const float* __restrict__ Bg,
              const float* __restrict__ bias, float* __restrict__ Cg,
              int K, int lda, int ldb, int ldc,
              size_t bA, size_t bB, size_t bC)
{
    constexpr int SROW = SPLIT ? 68 : 36;   // ≡4 mod 32 -> conflict-free fragment reads
    extern __shared__ float smf[];
    float* SA = smf;
    float* SB = smf + 128 * SROW;
    const uint32_t* UA = (const uint32_t*)SA;
    const uint32_t* UB = (const uint32_t*)SB;

    const int tid  = threadIdx.x;
    const int wid  = tid >> 5, lane = tid & 31;
    const int wm   = wid & 3,  wn   = wid >> 2;
    const int lr   = lane >> 2, lc  = lane & 3;
    const int rbase = tid >> 3;
    const int c4    = (tid & 7) * 4;

    const float* A = Ag + blockIdx.z * bA + (size_t)(blockIdx.y * 128) * lda;
    const float* B = Bg + blockIdx.z * bB + (size_t)(blockIdx.x * 128) * ldb;
    float*       C = Cg + blockIdx.z * bC + (size_t)(blockIdx.y * 128) * ldc + blockIdx.x * 128;

    float acc[2][8][4];
#pragma unroll
    for (int mi = 0; mi < 2; mi++)
#pragma unroll
        for (int nj = 0; nj < 8; nj++)
#pragma unroll
            for (int q = 0; q < 4; q++) acc[mi][nj][q] = 0.f;

    float4 pa[4], pb[4];
#pragma unroll
    for (int i = 0; i < 4; i++) {
        pa[i] = *(const float4*)(A + (size_t)(rbase + 32 * i) * lda + c4);
        pb[i] = *(const float4*)(B + (size_t)(rbase + 32 * i) * ldb + c4);
    }

    const int NCH = K / 32;
    for (int c = 0; c < NCH; c++) {
#pragma unroll
        for (int i = 0; i < 4; i++) {
            int r = rbase + 32 * i;
            if (SPLIT) {
                float4 hi, lo;
                hi.x = tf32rna(pa[i].x); lo.x = pa[i].x - hi.x;
                hi.y = tf32rna(pa[i].y); lo.y = pa[i].y - hi.y;
                hi.z = tf32rna(pa[i].z); lo.z = pa[i].z - hi.z;
                hi.w = tf32rna(pa[i].w); lo.w = pa[i].w - hi.w;
                *(float4*)(SA + r * SROW + c4)      = hi;
                *(float4*)(SA + r * SROW + 32 + c4) = lo;
                hi.x = tf32rna(pb[i].x); lo.x = pb[i].x - hi.x;
                hi.y = tf32rna(pb[i].y); lo.y = pb[i].y - hi.y;
                hi.z = tf32rna(pb[i].z); lo.z = pb[i].z - hi.z;
                hi.w = tf32rna(pb[i].w); lo.w = pb[i].w - hi.w;
                *(float4*)(SB + r * SROW + c4)      = hi;
                *(float4*)(SB + r * SROW + 32 + c4) = lo;
            } else {
                float4 v = pa[i];
                v.x = tf32rna(v.x); v.y = tf32rna(v.y);
                v.z = tf32rna(v.z); v.w = tf32rna(v.w);
                *(float4*)(SA + r * SROW + c4) = v;
                v = pb[i];
                v.x = tf32rna(v.x); v.y = tf32rna(v.y);
                v.z = tf32rna(v.z); v.w = tf32rna(v.w);
                *(float4*)(SB + r * SROW + c4) = v;
            }
        }
        __syncthreads();
        if (c + 1 < NCH) {
#pragma unroll
            for (int i = 0; i < 4; i++) {
                pa[i] = *(const float4*)(A + (size_t)(rbase + 32 * i) * lda + (c + 1) * 32 + c4);
                pb[i] = *(const float4*)(B + (size_t)(rbase + 32 * i) * ldb + (c + 1) * 32 + c4);
            }
        }
#pragma unroll
        for (int ks = 0; ks < 4; ks++) {
            const int k0 = ks * 8;
            uint32_t ah[2][4], bh[8][2];
#pragma unroll
            for (int mi = 0; mi < 2; mi++) {
                int base = (wm * 32 + mi * 16 + lr) * SROW + k0 + lc;
                ah[mi][0] = UA[base];            ah[mi][1] = UA[base + 8 * SROW];
                ah[mi][2] = UA[base + 4];        ah[mi][3] = UA[base + 8 * SROW + 4];
            }
#pragma unroll
            for (int nj = 0; nj < 8; nj++) {
                int base = (wn * 64 + nj * 8 + lr) * SROW + k0 + lc;
                bh[nj][0] = UB[base];            bh[nj][1] = UB[base + 4];
            }
#pragma unroll
            for (int mi = 0; mi < 2; mi++)
#pragma unroll
                for (int nj = 0; nj < 8; nj++)
                    mma8(acc[mi][nj], ah[mi], bh[nj]);
            if (SPLIT) {
                uint32_t al[2][4], bl[8][2];
#pragma unroll
                for (int mi = 0; mi < 2; mi++) {
                    int base = (wm * 32 + mi * 16 + lr) * SROW + 32 + k0 + lc;
                    al[mi][0] = UA[base];        al[mi][1] = UA[base + 8 * SROW];
                    al[mi][2] = UA[base + 4];    al[mi][3] = UA[base + 8 * SROW + 4];
                }
#pragma unroll
                for (int nj = 0; nj < 8; nj++) {
                    int base = (wn * 64 + nj * 8 + lr) * SROW + 32 + k0 + lc;
                    bl[nj][0] = UB[base];        bl[nj][1] = UB[base + 4];
                }
#pragma unroll
                for (int mi = 0; mi < 2; mi++)
#pragma unroll
                    for (int nj = 0; nj < 8; nj++) {
                        mma8(acc[mi][nj], ah[mi], bl[nj]);
                        mma8(acc[mi][nj], al[mi], bh[nj]);
                    }
            }
        }
        __syncthreads();
    }

#pragma unroll
    for (int mi = 0; mi < 2; mi++) {
        int r = wm * 32 + mi * 16 + lr;
        float b0 = 0.f, b1 = 0.f;
        if (ACT) {
            b0 = bias[blockIdx.y * 128 + r];
            b1 = bias[blockIdx.y * 128 + r + 8];
        }
#pragma unroll
        for (int nj = 0; nj < 8; nj++) {
            int col = wn * 64 + nj * 8 + lc * 2;
            float2 v0 = make_float2(acc[mi][nj][0], acc[mi][nj][1]);
            float2 v1 = make_float2(acc[mi][nj][2], acc[mi][nj][3]);
            if (ACT) {
                v0.x = relu6f(v0.x + b0); v0.y = relu6f(v0.y + b0);
                v1.x = relu6f(v1.x + b1); v1.y = relu6f(v1.y + b1);
            }
            *(float2*)(C + (size_t)r * ldc + col)       = v0;
            *(float2*)(C + (size_t)(r + 8) * ldc + col) = v1;
        }
    }
}

// ---------------- tensor-core 1x1 conv: C = relu6(W @ X + bias) -------------------
// A = W[r][k] row-major; B = X[k][n] (k-major gmem) read via [k][n] smem tile.
// Optional instance-norm of X. TRANSOUT=1 -> write C[n][r] (smem-staged transpose).
template<int SPLIT, int TRANSOUT>
__global__ __launch_bounds__(256, 1)
void conv_mma(const float* __restrict__ Wg, const float* __restrict__ Xg,
              const float* __restrict__ bias,
              const float* __restrict__ mean, const float* __restrict__ inv,
              float* __restrict__ Cg, int K, int ldc, size_t bC)
{
    constexpr int SROW = SPLIT ? 68 : 36;
    extern __shared__ float smf[];
    float* SA  = smf;                              // W tile [128r][SROW]
    float* XS0 = smf + 128 * SROW;                 // X tile hi [32k][132]
    float* XS1 = XS0 + (SPLIT ? 32 * 132 : 0);     // X tile lo
    float* stage = smf;                            // epilogue overlay [128n][132]
    const uint32_t* UA  = (const uint32_t*)SA;
    const uint32_t* UX0 = (const uint32_t*)XS0;
    const uint32_t* UX1 = (const uint32_t*)XS1;

    const int tid  = threadIdx.x;
    const int wid  = tid >> 5, lane = tid & 31;
    const int wm   = wid & 3,  wn   = wid >> 4 ? 1 : (wid >> 2);  // placeholder fix below
    const int wn2  = wid >> 2;
    const int lr   = lane >> 2, lc  = lane & 3;
    const int rbase = tid >> 3;
    const int c4    = (tid & 7) * 4;
    const int kk    = tid >> 5;          // 0..7 (k row group for X loads)
    const int n4    = (tid & 31) * 4;

    const int b  = blockIdx.z;
    const int n0 = blockIdx.x * 128;
    const int r0 = blockIdx.y * 128;
    const float* X = Xg + (size_t)b * K * NT;
    const float* mu = mean ? mean + b * K : nullptr;
    const float* iv = inv  ? inv  + b * K : nullptr;
    float* C = Cg + b * bC;

    float acc[2][8][4];
#pragma unroll
    for (int mi = 0; mi < 2; mi++)
#pragma unroll
        for (int nj = 0; nj < 8; nj++)
#pragma unroll
            for (int q = 0; q < 4; q++) acc[mi][nj][q] = 0.f;

    float4 pa[4], px[4];
    float pm[4], pv[4];
#pragma unroll
    for (int i = 0; i < 4; i++) {
        pa[i] = *(const float4*)(Wg + (size_t)(r0 + rbase + 32 * i) * K + c4);
        int k = kk + 8 * i;
        px[i] = *(const float4*)(X + (size_t)k * NT + n0 + n4);
        pm[i] = mu ? mu[k] : 0.f;
        pv[i] = iv ? iv[k] : 1.f;
    }

    const int NCH = K / 32;
    for (int c = 0; c < NCH; c++) {
        // store W tile
#pragma unroll
        for (int i = 0; i < 4; i++) {
            int r = rbase + 32 * i;
            if (SPLIT) {
                float4 hi, lo;
                hi.x = tf32rna(pa[i].x); lo.x = pa[i].x - hi.x;
                hi.y = tf32rna(pa[i].y); lo.y = pa[i].y - hi.y;
                hi.z = tf32rna(pa[i].z); lo.z = pa[i].z - hi.z;
                hi.w = tf32rna(pa[i].w); lo.w = pa[i].w - hi.w;
                *(float4*)(SA + r * SROW + c4)      = hi;
                *(float4*)(SA + r * SROW + 32 + c4) = lo;
            } else {
                float4 v = pa[i];
                v.x = tf32rna(v.x); v.y = tf32rna(v.y);
                v.z = tf32rna(v.z); v.w = tf32rna(v.w);
                *(float4*)(SA + r * SROW + c4) = v;
            }
        }
        // store X tile (normalized), [k][n] layout
#pragma unroll
        for (int i = 0; i < 4; i++) {
            int k = kk + 8 * i;
            float4 v = px[i];
            v.x = (v.x - pm[i]) * pv[i]; v.y = (v.y - pm[i]) * pv[i];
            v.z = (v.z - pm[i]) * pv[i]; v.w = (v.w - pm[i]) * pv[i];
            if (SPLIT) {
                float4 hi, lo;
                hi.x = tf32rna(v.x); lo.x = v.x - hi.x;
                hi.y = tf32rna(v.y); lo.y = v.y - hi.y;
                hi.z = tf32rna(v.z); lo.z = v.z - hi.z;
                hi.w = tf32rna(v.w); lo.w = v.w - hi.w;
                *(float4*)(XS0 + k * 132 + n4) = hi;
                *(float4*)(XS1 + k * 132 + n4) = lo;
            } else {
                v.x = tf32rna(v.x); v.y = tf32rna(v.y);
                v.z = tf32rna(v.z); v.w = tf32rna(v.w);
                *(float4*)(XS0 + k * 132 + n4) = v;
            }
        }
        __syncthreads();
        if (c + 1 < NCH) {
#pragma unroll
            for (int i = 0; i < 4; i++) {
                pa[i] = *(const float4*)(Wg + (size_t)(r0 + rbase + 32 * i) * K + (c + 1) * 32 + c4);
                int k = (c + 1) * 32 + kk + 8 * i;
                px[i] = *(const float4*)(X + (size_t)k * NT + n0 + n4);
                pm[i] = mu ? mu[k] : 0.f;
                pv[i] = iv ? iv[k] : 1.f;
            }
        }
#pragma unroll
        for (int ks = 0; ks < 4; ks++) {
            const int k0 = ks * 8;
            uint32_t ah[2][4], bh[8][2];
#pragma unroll
            for (int mi = 0; mi < 2; mi++) {
                int base = (wm * 32 + mi * 16 + lr) * SROW + k0 + lc;
                ah[mi][0] = UA[base];            ah[mi][1] = UA[base + 8 * SROW];
                ah[mi][2] = UA[base + 4];        ah[mi][3] = UA[base + 8 * SROW + 4];
            }
#pragma unroll
            for (int nj = 0; nj < 8; nj++) {
                int col = wn2 * 64 + nj * 8 + lr;
                bh[nj][0] = UX0[(k0 + lc) * 132 + col];
                bh[nj][1] = UX0[(k0 + lc + 4) * 132 + col];
            }
#pragma unroll
            for (int mi = 0; mi < 2; mi++)
#pragma unroll
                for (int nj = 0; nj < 8; nj++)
                    mma8(acc[mi][nj], ah[mi], bh[nj]);
            if (SPLIT) {
                uint32_t al[2][4], bl[8][2];
#pragma unroll
                for (int mi = 0; mi < 2; mi++) {
                    int base = (wm * 32 + mi * 16 + lr) * SROW + 32 + k0 + lc;
                    al[mi][0] = UA[base];        al[mi][1] = UA[base + 8 * SROW];
                    al[mi][2] = UA[base + 4];    al[mi][3] = UA[base + 8 * SROW + 4];
                }
#pragma unroll
                for (int nj = 0; nj < 8; nj++) {
                    int col = wn2 * 64 + nj * 8 + lr;
                    bl[nj][0] = UX1[(k0 + lc) * 132 + col];
                    bl[nj][1] = UX1[(k0 + lc + 4) * 132 + col];
                }
#pragma unroll
                for (int mi = 0; mi < 2; mi++)
#pragma unroll
                    for (int nj = 0; nj < 8; nj++) {
                        mma8(acc[mi][nj], ah[mi], bl[nj]);
                        mma8(acc[mi][nj], al[mi], bh[nj]);
                    }
            }
        }
        __syncthreads();
    }

    if (!TRANSOUT) {
        // C[r][n], ldc = NT
#pragma unroll
        for (int mi = 0; mi < 2; mi++) {
            int r = wm * 32 + mi * 16 + lr;
            float b0 = bias[r0 + r], b1 = bias[r0 + r + 8];
#pragma unroll
            for (int nj = 0; nj < 8; nj++) {
                int col = wn2 * 64 + nj * 8 + lc * 2;
                float2 v0 = make_float2(relu6f(acc[mi][nj][0] + b0),
                                        relu6f(acc[mi][nj][1] + b0));
                float2 v1 = make_float2(relu6f(acc[mi][nj][2] + b1),
                                        relu6f(acc[mi][nj][3] + b1));
                *(float2*)(C + (size_t)(r0 + r) * ldc + n0 + col)     = v0;
                *(float2*)(C + (size_t)(r0 + r + 8) * ldc + n0 + col) = v1;
            }
        }
    } else {
        // stage transposed, then write C[n][r], ldc = R
#pragma unroll
        for (int mi = 0; mi < 2; mi++) {
            int r = wm * 32 + mi * 16 + lr;
            float b0 = bias[r0 + r], b1 = bias[r0 + r + 8];
#pragma unroll
            for (int nj = 0; nj < 8; nj++) {
                int nl = wn2 * 64 + nj * 8 + lc * 2;
                stage[(size_t)nl * 132 + r]           = relu6f(acc[mi][nj][0] + b0);
                stage[(size_t)(nl + 1) * 132 + r]     = relu6f(acc[mi][nj][1] + b0);
                stage[(size_t)nl * 132 + r + 8]       = relu6f(acc[mi][nj][2] + b1);
                stage[(size_t)(nl + 1) * 132 + r + 8] = relu6f(acc[mi][nj][3] + b1);
            }
        }
        __syncthreads();
#pragma unroll
        for (int i = 0; i < 16; i++) {
            int e = tid + i * 256;
            int n = e >> 5, r4 = (e & 31) * 4;
            *(float4*)(C + (size_t)(n0 + n) * ldc + r0 + r4) = *(const float4*)(stage + n * 132 + r4);
        }
    }
}

// ---------------- row softmax over m (in-place on S), 4096 per row ----------------
__global__ __launch_bounds__(256) void softmax_kernel(float* __restrict__ S) {
    float* p = S + (size_t)blockIdx.x * NT;
    int tid = threadIdx.x;
    float4 v[4];
    float mx = -1e30f;
#pragma unroll
    for (int i = 0; i < 4; i++) {
        v[i] = ((const float4*)p)[tid + i * 256];
        mx = fmaxf(mx, fmaxf(fmaxf(v[i].x, v[i].y), fmaxf(v[i].z, v[i].w)));
    }
    __shared__ float redm[8], reds[8];
#pragma unroll
    for (int o = 16; o; o >>= 1) mx = fmaxf(mx, __shfl_xor_sync(0xffffffffu, mx, o));
    if ((tid & 31) == 0) redm[tid >> 5] = mx;
    __syncthreads();
    mx = fmaxf(fmaxf(fmaxf(redm[0], redm[1]), fmaxf(redm[2], redm[3])),
               fmaxf(fmaxf(redm[4], redm[5]), fmaxf(redm[6], redm[7])));
    float s = 0.f;
#pragma unroll
    for (int i = 0; i < 4; i++) {
        v[i].x = __expf(v[i].x - mx); v[i].y = __expf(v[i].y - mx);
        v[i].z = __expf(v[i].z - mx); v[i].w = __expf(v[i].w - mx);
        s += v[i].x + v[i].y + v[i].z + v[i].w;
    }
#pragma unroll
    for (int o = 16; o; o >>= 1) s += __shfl_xor_sync(0xffffffffu, s, o);
    if ((tid & 31) == 0) reds[tid >> 5] = s;
    __syncthreads();
    s = reds[0] + reds[1] + reds[2] + reds[3] + reds[4] + reds[5] + reds[6] + reds[7];
    float inv = 1.f / s;
#pragma unroll
    for (int i = 0; i < 4; i++) {
        v[i].x *= inv; v[i].y *= inv; v[i].z *= inv; v[i].w *= inv;
        ((float4*)p)[tid + i * 256] = v[i];
    }
}

// ---------------- launch ----------------
extern "C" void kernel_launch(void* const* d_in, const int* in_sizes, int n_in,
                              void* d_out, int out_size) {
    const float* Fc    = (const float*)d_in[0];
    const float* Fs    = (const float*)d_in[1];
    const float* f_w   = (const float*)d_in[2];
    const float* f_b   = (const float*)d_in[3];
    const float* g_w   = (const float*)d_in[4];
    const float* g_b   = (const float*)d_in[5];
    const float* h_w   = (const float*)d_in[6];
    const float* h_b   = (const float*)d_in[7];
    const float* out_w = (const float*)d_in[8];
    const float* out_b = (const float*)d_in[9];
    float* out = (float*)d_out;

    float *pfT, *pgT, *ph, *pfcs, *pS, *pmean, *pinv;
    cudaGetSymbolAddress((void**)&pfT,   d_fT);
    cudaGetSymbolAddress((void**)&pgT,   d_gT);
    cudaGetSymbolAddress((void**)&ph,    d_h);
    cudaGetSymbolAddress((void**)&pfcs,  d_fcs);
    cudaGetSymbolAddress((void**)&pS,    d_S);
    cudaGetSymbolAddress((void**)&pmean, d_mean);
    cudaGetSymbolAddress((void**)&pinv,  d_inv);

    const int SM_G1 = 2 * 128 * 68 * 4;                 // 69632 (split gemm)
    const int SM_G0 = 2 * 128 * 36 * 4;                 // 36864
    const int SM_C1 = (128 * 68 + 2 * 32 * 132) * 4;    // 68608 (split conv, >= stage 67584)
    const int SM_C0 = (128 * 36 + 32 * 132) * 4;        // 35328
    cudaFuncSetAttribute(mma_gemm<1, 0>, cudaFuncAttributeMaxDynamicSharedMemorySize, SM_G1);
    cudaFuncSetAttribute(mma_gemm<0, 0>, cudaFuncAttributeMaxDynamicSharedMemorySize, SM_G0);
    cudaFuncSetAttribute(mma_gemm<0, 1>, cudaFuncAttributeMaxDynamicSharedMemorySize, SM_G0);
    cudaFuncSetAttribute(conv_mma<1, 1>, cudaFuncAttributeMaxDynamicSharedMemorySize, SM_C1);
    cudaFuncSetAttribute(conv_mma<0, 0>, cudaFuncAttributeMaxDynamicSharedMemorySize, SM_C0);

    stats_kernel<<<dim3(BATCH * CIN, 2), 256>>>(Fc, Fs);

    // fT[n][d] = relu6(f_w @ mvn(Fc) + f_b)^T   (3xtf32)
    conv_mma<1, 1><<<dim3(NT / 128, CH / 128, BATCH), 256, SM_C1>>>(
        f_w, Fc, f_b, pmean, pinv, pfT, CIN, CH, (size_t)NT * CH);
    // gT[m][d] = relu6(g_w @ mvn(Fs) + g_b)^T   (3xtf32)
    conv_mma<1, 1><<<dim3(NT / 128, CH / 128, BATCH), 256, SM_C1>>>(
        g_w, Fs, g_b, pmean + BATCH * CIN, pinv + BATCH * CIN, pgT, CIN, CH, (size_t)NT * CH);
    // h[d][m] = relu6(h_w @ Fs + h_b)           (1xtf32)
    conv_mma<0, 0><<<dim3(NT / 128, CH / 128, BATCH), 256, SM_C0>>>(
        h_w, Fs, h_b, nullptr, nullptr, ph, CIN, NT, (size_t)CH * NT);

    // S[n][m] = fT . gT^T   (3xtf32)
    mma_gemm<1, 0><<<dim3(NT / 128, NT / 128, BATCH), 256, SM_G1>>>(
        pfT, pgT, nullptr, pS, CH, CH, CH, NT,
        (size_t)NT * CH, (size_t)NT * CH, (size_t)NT * NT);

    // P = softmax_m(S), in place
    softmax_kernel<<<BATCH * NT, 256>>>(pS);

    // fcs[n][d] = P . h^T   (1xtf32)
    mma_gemm<0, 0><<<dim3(CH / 128, NT / 128, BATCH), 256, SM_G0>>>(
        pS, ph, nullptr, pfcs, NT, NT, NT, CH,
        (size_t)NT * NT, (size_t)CH * NT, (size_t)NT * CH);

    // out[r][n] = relu6(out_w @ fcs^T + out_b)  (1xtf32)
    mma_gemm<0, 1><<<dim3(NT / 128, CIN / 128, BATCH), 256, SM_G0>>>(
        out_w, pfcs, out_b, out, CH, CH, CH, NT,
        (size_t)0, (size_t)NT * CH, (size_t)CIN * NT);
}